// round 11
// baseline (speedup 1.0000x reference)
#include <cuda_runtime.h>
#include <cuda_bf16.h>
#include <cstdint>

// ---------------------------------------------------------------------------
// Problem constants
// ---------------------------------------------------------------------------
#define MAXN 50000
#define D_IN 128
#define D_OUT 128
#define D_NODEREP 134  // 128 + 6
#define DH 256
#define EPS 1e-5f

#define TILE_E 64
#define ETHREADS 256

// smem strides (floats) — conflict-free mma fragment LDS
#define S_H 132        // mod 32 = 4
#define S_WA 136       // 128-col weight chunks (mod 32 = 8)
#define S_WB 264       // 256-col weight chunks (mod 32 = 8)

// ---- edge kernel smem layout (floats) ----
#define HBUF_OFF 0
#define HBUF_FLOATS (TILE_E * S_H)             // 8448
#define TZ_OFF HBUF_FLOATS                     // featz / t-half overlay
#define TZ_FLOATS (TILE_E * S_H)               // 8448
#define WB_OFF (TZ_OFF + TZ_FLOATS)            // 16896
#define WB_SLOT 2176                           // 16 rows * 136
#define E_SMEM_FLOATS (WB_OFF + 4 * WB_SLOT)   // 25600 floats = 102.4 KB

// ---- node projection kernel ----
#define TILE_N 64
#define NPTHREADS 256
#define KPAD_P 144     // 134 padded to 16*9
#define NCH_P 9
#define S_P 164        // mod 32 = 4
#define NP_A_FLOATS (TILE_N * S_P)             // 10496
#define NP_WBUF 4224                           // 16 * 264
#define NP_SMEM_FLOATS (NP_A_FLOATS + 2 * NP_WBUF)  // 18944 floats = 75.8 KB

// Scratch (static device globals: no allocation allowed)
__device__ float g_agg[(size_t)MAXN * D_IN];
__device__ float g_den[MAXN];
__device__ float g_P[(size_t)MAXN * 256];      // [N][Pa(128) | Pb(128)]

// ---------------------------------------------------------------------------
// helpers
// ---------------------------------------------------------------------------
__device__ __forceinline__ unsigned f2tf(float f) {
    unsigned u;
    asm("cvt.rna.tf32.f32 %0, %1;" : "=r"(u) : "f"(f));
    return u;
}

// paired-k permutation within each 8-column block: pairs (k, k+4) adjacent.
// perm(c) = (c & ~7) + 2*(c & 3) + ((c >> 2) & 1)
__device__ __forceinline__ int permc(int c) {
    return (c & ~7) + 2 * (c & 3) + ((c >> 2) & 1);
}

__device__ __forceinline__ void mma_tf32(float* c, const unsigned* a,
                                         unsigned b0, unsigned b1) {
    asm volatile(
        "mma.sync.aligned.m16n8k8.row.col.f32.tf32.tf32.f32 "
        "{%0,%1,%2,%3},{%4,%5,%6,%7},{%8,%9},{%0,%1,%2,%3};\n"
        : "+f"(c[0]), "+f"(c[1]), "+f"(c[2]), "+f"(c[3])
        : "r"(a[0]), "r"(a[1]), "r"(a[2]), "r"(a[3]), "r"(b0), "r"(b1));
}

__device__ __forceinline__ void cp16(float* dst_smem, const float* src, bool pred) {
    unsigned d = (unsigned)__cvta_generic_to_shared(dst_smem);
    int sz = pred ? 16 : 0;
    asm volatile("cp.async.cg.shared.global [%0], [%1], 16, %2;\n"
                 :: "r"(d), "l"(src), "r"(sz));
}
__device__ __forceinline__ void cp_commit() {
    asm volatile("cp.async.commit_group;\n");
}
template <int N>
__device__ __forceinline__ void cp_wait() {
    asm volatile("cp.async.wait_group %0;\n" :: "n"(N));
}

// ---------------------------------------------------------------------------
// Kernel 1: zero the scratch (float4)
// ---------------------------------------------------------------------------
__global__ void zero_kernel(int N) {
    int idx = blockIdx.x * blockDim.x + threadIdx.x;
    int total4 = N * (D_IN / 4);
    if (idx < total4) ((float4*)g_agg)[idx] = make_float4(0.f, 0.f, 0.f, 0.f);
    if (idx < N) g_den[idx] = 0.f;
}

// ---------------------------------------------------------------------------
// Kernel 2: masked scatter-add aggregation (warp per edge, float4 atomics)
// ---------------------------------------------------------------------------
__global__ void agg_kernel(const float* __restrict__ edge_attr,
                           const float* __restrict__ mask,
                           const int* __restrict__ edge_index, int E) {
    int w = (blockIdx.x * blockDim.x + threadIdx.x) >> 5;
    int lane = threadIdx.x & 31;
    if (w >= E) return;
    float m = mask[w];
    if (m == 0.f) return;
    int col = edge_index[E + w];
    const float4* a = (const float4*)(edge_attr + (size_t)w * D_IN);
    float4* dst = (float4*)(g_agg + (size_t)col * D_IN);
    float4 v = a[lane];
    v.x *= m; v.y *= m; v.z *= m; v.w *= m;
    atomicAdd(dst + lane, v);
    if (lane == 0) atomicAdd(g_den + col, m);
}

// ---------------------------------------------------------------------------
// Kernel 3: node projection  P = node_rep @ [We_a | We_b]   (N x 256)
// Also materializes node_rep into out_node.  3 blocks/SM.
// ---------------------------------------------------------------------------
__global__ void __launch_bounds__(NPTHREADS, 3)
nodeproj_kernel(const float* __restrict__ x,
                const float* __restrict__ We,
                float* __restrict__ out_node, int N) {
    extern __shared__ float sm[];
    float* A = sm;
    float* wb = sm + NP_A_FLOATS;
    __shared__ float rden_s[TILE_N];

    const int tid = threadIdx.x;
    const int lane = tid & 31;
    const int wid = tid >> 5;
    const int n0blk = blockIdx.x * TILE_N;

    const int m0 = 16 * (wid >> 1);
    const int n0 = 128 * (wid & 1);
    const int r0 = lane >> 2;
    const int qk = lane & 3;
    const int cb = 2 * qk;

    auto issue_w = [&](int ch, int stage) {  // 16 rows x 256 cols (Wea|Web)
        float* dst = wb + stage * NP_WBUF;
        int kb = ch * 16;
#pragma unroll
        for (int j = 0; j < 4; j++) {
            int i = tid + j * NPTHREADS;
            int r = i >> 6;
            int c4 = (i & 63) * 4;
            int k = kb + r;
            const float* src = (c4 < 128)
                ? We + (size_t)k * D_OUT + c4
                : We + (size_t)(D_NODEREP + k) * D_OUT + (c4 - 128);
            cp16(dst + r * S_WB + c4, src, k < D_NODEREP);
        }
        cp_commit();
    };

    issue_w(0, 0);

    if (tid < TILE_N) {
        int n = n0blk + tid;
        float d = (n < N) ? g_den[n] : 0.f;
        rden_s[tid] = 1.0f / (d + 1.0f);
    }
    __syncthreads();

    for (int idx = tid; idx < TILE_N * KPAD_P; idx += NPTHREADS) {
        int e = idx / KPAD_P;
        int k = idx - e * KPAD_P;
        int n = n0blk + e;
        float v = 0.f;
        if (n < N && k < D_NODEREP) {
            if (k < D_IN)
                v = g_agg[(size_t)n * D_IN + k] * rden_s[e];
            else
                v = x[n * 6 + (k - D_IN)];
            out_node[(size_t)n * D_NODEREP + k] = v;
        }
        A[e * S_P + k] = v;
    }

    float acc[16][4];
#pragma unroll
    for (int nt = 0; nt < 16; nt++)
#pragma unroll
        for (int q = 0; q < 4; q++) acc[nt][q] = 0.f;

    for (int ch = 0; ch < NCH_P; ch++) {
        cp_wait<0>();
        __syncthreads();
        if (ch + 1 < NCH_P) issue_w(ch + 1, (ch + 1) & 1);
        const float* cur = wb + (ch & 1) * NP_WBUF;
#pragma unroll
        for (int ks = 0; ks < 2; ks++) {
            int k0 = ch * 16 + ks * 8;
            const float* ap = A + (m0 + r0) * S_P + k0 + qk;
            unsigned a[4];
            a[0] = f2tf(ap[0]);
            a[1] = f2tf(ap[8 * S_P]);
            a[2] = f2tf(ap[4]);
            a[3] = f2tf(ap[8 * S_P + 4]);
#pragma unroll
            for (int nt = 0; nt < 16; nt++) {
                const float* bp = cur + (ks * 8 + qk) * S_WB + n0 + 8 * nt + r0;
                mma_tf32(acc[nt], a, __float_as_uint(bp[0]),
                         __float_as_uint(bp[4 * S_WB]));
            }
        }
    }

#pragma unroll
    for (int nt = 0; nt < 16; nt++) {
        int col = n0 + 8 * nt + cb;
#pragma unroll
        for (int q = 0; q < 4; q++) {
            int rr = m0 + r0 + (q >> 1) * 8;
            int cc = col + (q & 1);
            int n = n0blk + rr;
            if (n < N) g_P[(size_t)n * 256 + cc] = acc[nt][q];
        }
    }
}

// ---------------------------------------------------------------------------
// Kernel 4: fused edge MLP, register-resident LayerNorms, paired-k A layout
// for the h/t buffers (GEMM2/3 A fragments load as 2x LDS.64).
// 64 edges/block, 256 threads (8 warps, warp tile m32 x n32), 2 blocks/SM.
// Weight ring: 4 slots x 16 rows, depth-3 cp.async prefetch.
// Race-free ordering: wait -> barrier -> compute(ch) -> issue(ch+3).
// ---------------------------------------------------------------------------
__global__ void __launch_bounds__(ETHREADS, 2)
edge_kernel(const float* __restrict__ edge_attr,
            const int* __restrict__ edge_index,
            const float* __restrict__ We, const float* __restrict__ bE,
            const float* __restrict__ W1, const float* __restrict__ b1,
            const float* __restrict__ W2, const float* __restrict__ b2,
            const float* __restrict__ g1, const float* __restrict__ be1,
            const float* __restrict__ g2, const float* __restrict__ be2,
            float* __restrict__ out, int E) {
    extern __shared__ float sm[];
    float* hbuf = sm + HBUF_OFF;
    float* tz = sm + TZ_OFF;    // featz -> t-half overlay
    float* wb = sm + WB_OFF;
    __shared__ int rows_s[TILE_E], cols_s[TILE_E];
    __shared__ float red_s[TILE_E][4];    // per-row per-n-warp partial sums
    __shared__ float red_s2[TILE_E][4];
    __shared__ float mu_s[TILE_E], rinv_s[TILE_E];

    const int tid = threadIdx.x;
    const int lane = tid & 31;
    const int wid = tid >> 5;
    const int e0 = blockIdx.x * TILE_E;

    const int m0 = 32 * (wid & 1);     // 0 or 32
    const int warp_n = wid >> 1;       // 0..3
    const int n032 = 32 * warp_n;
    const int r0 = lane >> 2;
    const int qk = lane & 3;
    const int cb = 2 * qk;

    auto issue_wec = [&](int ch, int slot) {  // We_c rows 268+16ch..
        float* dst = wb + slot * WB_SLOT;
        int kb = ch * 16;
#pragma unroll
        for (int j = 0; j < 2; j++) {
            int i = tid + j * ETHREADS;
            int r = i >> 5, c4 = (i & 31) * 4;
            cp16(dst + r * S_WA + c4,
                 We + (size_t)(2 * D_NODEREP + kb + r) * D_OUT + c4, true);
        }
        cp_commit();
    };
    auto issue_w1h = [&](int hf, int ch, int slot) {  // W1 16 x 128 (col half)
        float* dst = wb + slot * WB_SLOT;
        int kb = ch * 16;
#pragma unroll
        for (int j = 0; j < 2; j++) {
            int i = tid + j * ETHREADS;
            int r = i >> 5, c4 = (i & 31) * 4;
            cp16(dst + r * S_WA + c4,
                 W1 + (size_t)(kb + r) * DH + hf * 128 + c4, true);
        }
        cp_commit();
    };
    auto issue_w2h = [&](int hf, int ch, int slot) {  // W2 16 x 128 (row half)
        float* dst = wb + slot * WB_SLOT;
        int kb = hf * 128 + ch * 16;
#pragma unroll
        for (int j = 0; j < 2; j++) {
            int i = tid + j * ETHREADS;
            int r = i >> 5, c4 = (i & 31) * 4;
            cp16(dst + r * S_WA + c4, W2 + (size_t)(kb + r) * D_OUT + c4, true);
        }
        cp_commit();
    };

    if (tid < TILE_E) {
        int eg = e0 + tid;
        rows_s[tid] = (eg < E) ? edge_index[eg] : 0;
        cols_s[tid] = (eg < E) ? edge_index[E + eg] : 0;
    }

    // GEMM1 prologue (depth 3) — overlaps the gathers below
    issue_wec(0, 0);
    issue_wec(1, 1);
    issue_wec(2, 2);

    // edge_attr tile -> tz (featz), float4 coalesced, PRE-ROUNDED to tf32
    // featz stays UNPERMUTED (GEMM1 A uses scalar loads; residual float2 reads)
    for (int idx = tid; idx < TILE_E * 32; idx += ETHREADS) {
        int e = idx >> 5;
        int c4 = (idx & 31) * 4;
        int eg = e0 + e;
        float4 v = make_float4(0.f, 0.f, 0.f, 0.f);
        if (eg < E) v = *(const float4*)(edge_attr + (size_t)eg * D_IN + c4);
        v.x = __uint_as_float(f2tf(v.x));
        v.y = __uint_as_float(f2tf(v.y));
        v.z = __uint_as_float(f2tf(v.z));
        v.w = __uint_as_float(f2tf(v.w));
        *(float4*)(tz + e * S_H + c4) = v;
    }
    __syncthreads();  // rows_s/cols_s ready

    // hbuf = Pa[row] + Pb[col]  (float4 gather from L2-resident P, fp32,
    // unpermuted — consumed by GEMM1 epilogue before h overwrites it)
    for (int idx = tid; idx < TILE_E * 32; idx += ETHREADS) {
        int e = idx >> 5;
        int c4 = (idx & 31) * 4;
        float4 pa = *(const float4*)(g_P + (size_t)rows_s[e] * 256 + c4);
        float4 pb = *(const float4*)(g_P + (size_t)cols_s[e] * 256 + 128 + c4);
        pa.x += pb.x; pa.y += pb.y; pa.z += pb.z; pa.w += pb.w;
        *(float4*)(hbuf + e * S_H + c4) = pa;
    }

    // ================= GEMM1: featz[64,128] @ We_c[128,128] ==============
    float acc1[2][4][4];
#pragma unroll
    for (int mt = 0; mt < 2; mt++)
#pragma unroll
        for (int nt = 0; nt < 4; nt++)
#pragma unroll
            for (int q = 0; q < 4; q++) acc1[mt][nt][q] = 0.f;

    {
        const int NCH = 8;
        for (int ch = 0; ch < NCH; ch++) {
            if (ch < NCH - 2) cp_wait<2>();
            else if (ch == NCH - 2) cp_wait<1>();
            else cp_wait<0>();
            __syncthreads();
            const float* cur = wb + (ch & 3) * WB_SLOT;
#pragma unroll
            for (int ks = 0; ks < 2; ks++) {
                int k0 = ch * 16 + ks * 8;
                unsigned a[2][4];
#pragma unroll
                for (int mt = 0; mt < 2; mt++) {
                    const float* ap = tz + (m0 + 16 * mt + r0) * S_H + k0 + qk;
                    a[mt][0] = __float_as_uint(ap[0]);
                    a[mt][1] = __float_as_uint(ap[8 * S_H]);
                    a[mt][2] = __float_as_uint(ap[4]);
                    a[mt][3] = __float_as_uint(ap[8 * S_H + 4]);
                }
#pragma unroll
                for (int nt = 0; nt < 4; nt++) {
                    const float* bp = cur + (ks * 8 + qk) * S_WA + n032 + 8 * nt + r0;
                    unsigned b0 = __float_as_uint(bp[0]);
                    unsigned b1w = __float_as_uint(bp[4 * S_WA]);
                    mma_tf32(acc1[0][nt], a[0], b0, b1w);
                    mma_tf32(acc1[1][nt], a[1], b0, b1w);
                }
            }
            if (ch + 3 < NCH) issue_wec(ch + 3, (ch + 3) & 3);
        }
    }

    // GEMM2(hf=0) prologue — slots 0,1,2 last read at ch 4,5,6 (all done)
    issue_w1h(0, 0, 0);
    issue_w1h(0, 1, 1);
    issue_w1h(0, 2, 2);

    // ---- GEMM1 epilogue with fused LN1 (register-resident) ----
#pragma unroll
    for (int mt = 0; mt < 2; mt++)
#pragma unroll
        for (int nt = 0; nt < 4; nt++) {
            int col = n032 + 8 * nt + cb;
            float2 bev = *(const float2*)(bE + col);
#pragma unroll
            for (int rh = 0; rh < 2; rh++) {
                int rr = m0 + 16 * mt + r0 + 8 * rh;
                float2 fz = *(float2*)(tz + rr * S_H + col);
                float2 pv = *(float2*)(hbuf + rr * S_H + col);
                acc1[mt][nt][2 * rh + 0] += bev.x + fz.x + pv.x;
                acc1[mt][nt][2 * rh + 1] += bev.y + fz.y + pv.y;
            }
        }
#pragma unroll
    for (int mt = 0; mt < 2; mt++)
#pragma unroll
        for (int rh = 0; rh < 2; rh++) {
            float s = 0.f, s2 = 0.f;
#pragma unroll
            for (int nt = 0; nt < 4; nt++)
#pragma unroll
                for (int b = 0; b < 2; b++) {
                    float v = acc1[mt][nt][2 * rh + b];
                    s += v; s2 += v * v;
                }
            s += __shfl_xor_sync(0xFFFFFFFF, s, 1);
            s += __shfl_xor_sync(0xFFFFFFFF, s, 2);
            s2 += __shfl_xor_sync(0xFFFFFFFF, s2, 1);
            s2 += __shfl_xor_sync(0xFFFFFFFF, s2, 2);
            if (qk == 0) {
                int rr = m0 + 16 * mt + r0 + 8 * rh;
                red_s[rr][warp_n] = s;
                red_s2[rr][warp_n] = s2;
            }
        }
    __syncthreads();
    if (tid < TILE_E) {
        float s = red_s[tid][0] + red_s[tid][1] + red_s[tid][2] + red_s[tid][3];
        float s2 = red_s2[tid][0] + red_s2[tid][1] + red_s2[tid][2] + red_s2[tid][3];
        float mu = s * (1.f / 128.f);
        float var = s2 * (1.f / 128.f) - mu * mu;
        mu_s[tid] = mu;
        rinv_s[tid] = rsqrtf(var + EPS);
    }
    __syncthreads();
    // normalize from regs, store h (tf32-rounded) to hbuf in PAIRED-K layout
#pragma unroll
    for (int mt = 0; mt < 2; mt++)
#pragma unroll
        for (int nt = 0; nt < 4; nt++) {
            int col = n032 + 8 * nt + cb;
            int p0 = permc(col);  // pair stores at p0, p0+2
            float2 gv = *(const float2*)(g1 + col);
            float2 bv = *(const float2*)(be1 + col);
#pragma unroll
            for (int rh = 0; rh < 2; rh++) {
                int rr = m0 + 16 * mt + r0 + 8 * rh;
                float mu = mu_s[rr], ri = rinv_s[rr];
                float h0 = (acc1[mt][nt][2 * rh + 0] - mu) * ri * gv.x + bv.x;
                float h1 = (acc1[mt][nt][2 * rh + 1] - mu) * ri * gv.y + bv.y;
                hbuf[rr * S_H + p0] = __uint_as_float(f2tf(h0));
                hbuf[rr * S_H + p0 + 2] = __uint_as_float(f2tf(h1));
            }
        }

    // ============ GEMM2+GEMM3 in two 128-halves, acc3 persistent =========
    float acc3[2][4][4];
#pragma unroll
    for (int mt = 0; mt < 2; mt++)
#pragma unroll
        for (int nt = 0; nt < 4; nt++)
#pragma unroll
            for (int q = 0; q < 4; q++) acc3[mt][nt][q] = 0.f;

#pragma unroll 1
    for (int hf = 0; hf < 2; hf++) {
        // ---- GEMM2 half: t_half = relu(h @ W1[:, hf*128:+128] + b1h) ----
        {
            float acc2[2][4][4];
#pragma unroll
            for (int mt = 0; mt < 2; mt++)
#pragma unroll
                for (int nt = 0; nt < 4; nt++)
#pragma unroll
                    for (int q = 0; q < 4; q++) acc2[mt][nt][q] = 0.f;

            if (hf) {  // hf=0 prologue hoisted before LN1
                issue_w1h(hf, 0, 0);
                issue_w1h(hf, 1, 1);
                issue_w1h(hf, 2, 2);
            }
            const int NCH = 8;
            for (int ch = 0; ch < NCH; ch++) {
                if (ch < NCH - 2) cp_wait<2>();
                else if (ch == NCH - 2) cp_wait<1>();
                else cp_wait<0>();
                __syncthreads();
                const float* cur = wb + (ch & 3) * WB_SLOT;
#pragma unroll
                for (int ks = 0; ks < 2; ks++) {
                    int k0 = ch * 16 + ks * 8;
                    unsigned a[2][4];
#pragma unroll
                    for (int mt = 0; mt < 2; mt++) {
                        // paired-k layout: float2 = (k0+qk, k0+qk+4)
                        const float* ap = hbuf + (m0 + 16 * mt + r0) * S_H + k0 + 2 * qk;
                        float2 lo = *(const float2*)ap;
                        float2 hi = *(const float2*)(ap + 8 * S_H);
                        a[mt][0] = __float_as_uint(lo.x);
                        a[mt][2] = __float_as_uint(lo.y);
                        a[mt][1] = __float_as_uint(hi.x);
                        a[mt][3] = __float_as_uint(hi.y);
                    }
#pragma unroll
                    for (int nt = 0; nt < 4; nt++) {
                        const float* bp = cur + (ks * 8 + qk) * S_WA + n032 + 8 * nt + r0;
                        unsigned b0 = __float_as_uint(bp[0]);
                        unsigned b1w = __float_as_uint(bp[4 * S_WA]);
                        mma_tf32(acc2[0][nt], a[0], b0, b1w);
                        mma_tf32(acc2[1][nt], a[1], b0, b1w);
                    }
                }
                if (ch + 3 < NCH) issue_w1h(hf, ch + 3, (ch + 3) & 3);
            }
            __syncthreads();  // ring reads done; tz free to write

            // hoist GEMM3 prologue — copies land during t-store
            issue_w2h(hf, 0, 0);
            issue_w2h(hf, 1, 1);
            issue_w2h(hf, 2, 2);

            // t_half -> tz in PAIRED-K layout (tf32-rounded, GEMM3 A operand)
#pragma unroll
            for (int mt = 0; mt < 2; mt++)
#pragma unroll
                for (int nt = 0; nt < 4; nt++) {
                    int col = n032 + 8 * nt + cb;
                    int p0 = permc(col);
                    float2 b1v = *(const float2*)(b1 + hf * 128 + col);
#pragma unroll
                    for (int rh = 0; rh < 2; rh++) {
                        int rr = m0 + 16 * mt + r0 + 8 * rh;
                        float t0 = fmaxf(acc2[mt][nt][2 * rh + 0] + b1v.x, 0.f);
                        float t1 = fmaxf(acc2[mt][nt][2 * rh + 1] + b1v.y, 0.f);
                        tz[rr * S_H + p0] = __uint_as_float(f2tf(t0));
                        tz[rr * S_H + p0 + 2] = __uint_as_float(f2tf(t1));
                    }
                }
        }
        __syncthreads();

        // ---- GEMM3 half: acc3 += t_half @ W2[hf*128:+128, :] ----
        {
            const int NCH = 8;
            for (int ch = 0; ch < NCH; ch++) {
                if (ch < NCH - 2) cp_wait<2>();
                else if (ch == NCH - 2) cp_wait<1>();
                else cp_wait<0>();
                __syncthreads();
                const float* cur = wb + (ch & 3) * WB_SLOT;
#pragma unroll
                for (int ks = 0; ks < 2; ks++) {
                    int k0 = ch * 16 + ks * 8;
                    unsigned a[2][4];
#pragma unroll
                    for (int mt = 0; mt < 2; mt++) {
                        const float* ap = tz + (m0 + 16 * mt + r0) * S_H + k0 + 2 * qk;
                        float2 lo = *(const float2*)ap;
                        float2 hi = *(const float2*)(ap + 8 * S_H);
                        a[mt][0] = __float_as_uint(lo.x);
                        a[mt][2] = __float_as_uint(lo.y);
                        a[mt][1] = __float_as_uint(hi.x);
                        a[mt][3] = __float_as_uint(hi.y);
                    }
#pragma unroll
                    for (int nt = 0; nt < 4; nt++) {
                        const float* bp = cur + (ks * 8 + qk) * S_WA + n032 + 8 * nt + r0;
                        unsigned b0 = __float_as_uint(bp[0]);
                        unsigned b1w = __float_as_uint(bp[4 * S_WA]);
                        mma_tf32(acc3[0][nt], a[0], b0, b1w);
                        mma_tf32(acc3[1][nt], a[1], b0, b1w);
                    }
                }
                if (ch + 3 < NCH) issue_w2h(hf, ch + 3, (ch + 3) & 3);
            }
        }
        __syncthreads();  // tz reads done before next hf overwrites it
    }

    // ---- GEMM3 epilogue with fused LN2 (register-resident) -> global ----
    // z = acc3 + b2 + h(hbuf, paired-k layout)
#pragma unroll
    for (int mt = 0; mt < 2; mt++)
#pragma unroll
        for (int nt = 0; nt < 4; nt++) {
            int col = n032 + 8 * nt + cb;
            int p0 = permc(col);
            float2 b2v = *(const float2*)(b2 + col);
#pragma unroll
            for (int rh = 0; rh < 2; rh++) {
                int rr = m0 + 16 * mt + r0 + 8 * rh;
                float h0 = hbuf[rr * S_H + p0];
                float h1 = hbuf[rr * S_H + p0 + 2];
                acc3[mt][nt][2 * rh + 0] += b2v.x + h0;
                acc3[mt][nt][2 * rh + 1] += b2v.y + h1;
            }
        }
#pragma unroll
    for (int mt = 0; mt < 2; mt++)
#pragma unroll
        for (int rh = 0; rh < 2; rh++) {
            float s = 0.f, s2 = 0.f;
#pragma unroll
            for (int nt = 0; nt < 4; nt++)
#pragma unroll
                for (int b = 0; b < 2; b++) {
                    float v = acc3[mt][nt][2 * rh + b];
                    s += v; s2 += v * v;
                }
            s += __shfl_xor_sync(0xFFFFFFFF, s, 1);
            s += __shfl_xor_sync(0xFFFFFFFF, s, 2);
            s2 += __shfl_xor_sync(0xFFFFFFFF, s2, 1);
            s2 += __shfl_xor_sync(0xFFFFFFFF, s2, 2);
            if (qk == 0) {
                int rr = m0 + 16 * mt + r0 + 8 * rh;
                red_s[rr][warp_n] = s;
                red_s2[rr][warp_n] = s2;
            }
        }
    __syncthreads();
    if (tid < TILE_E) {
        float s = red_s[tid][0] + red_s[tid][1] + red_s[tid][2] + red_s[tid][3];
        float s2 = red_s2[tid][0] + red_s2[tid][1] + red_s2[tid][2] + red_s2[tid][3];
        float mu = s * (1.f / 128.f);
        float var = s2 * (1.f / 128.f) - mu * mu;
        mu_s[tid] = mu;
        rinv_s[tid] = rsqrtf(var + EPS);
    }
    __syncthreads();
#pragma unroll
    for (int mt = 0; mt < 2; mt++)
#pragma unroll
        for (int nt = 0; nt < 4; nt++) {
            int col = n032 + 8 * nt + cb;
            float2 gv = *(const float2*)(g2 + col);
            float2 bv = *(const float2*)(be2 + col);
#pragma unroll
            for (int rh = 0; rh < 2; rh++) {
                int rr = m0 + 16 * mt + r0 + 8 * rh;
                int eg = e0 + rr;
                if (eg < E) {
                    float mu = mu_s[rr], ri = rinv_s[rr];
                    float2 ov;
                    ov.x = (acc3[mt][nt][2 * rh + 0] - mu) * ri * gv.x + bv.x;
                    ov.y = (acc3[mt][nt][2 * rh + 1] - mu) * ri * gv.y + bv.y;
                    *(float2*)(out + (size_t)eg * D_OUT + col) = ov;
                }
            }
        }
}

// ---------------------------------------------------------------------------
// launch
// ---------------------------------------------------------------------------
extern "C" void kernel_launch(void* const* d_in, const int* in_sizes, int n_in,
                              void* d_out, int out_size) {
    const void* p[16];
    int sz[16];
    int m = 0;
    for (int i = 0; i < n_in && m < 16; i++) {
        if (in_sizes[i] == 1) continue;
        p[m] = d_in[i];
        sz[m] = in_sizes[i];
        m++;
    }
    const float* x          = (const float*)p[0];
    const int*   edge_index = (const int*)p[1];
    const float* edge_attr  = (const float*)p[2];
    const float* mask       = (const float*)p[3];
    const float* We         = (const float*)p[4];
    const float* bE         = (const float*)p[5];
    const float* W1         = (const float*)p[6];
    const float* b1         = (const float*)p[7];
    const float* W2         = (const float*)p[8];
    const float* b2         = (const float*)p[9];
    const float* g1         = (const float*)p[10];
    const float* be1        = (const float*)p[11];
    const float* g2         = (const float*)p[12];
    const float* be2        = (const float*)p[13];

    const int N = sz[0] / 6;
    const int E = sz[3];

    float* out_node = (float*)d_out;                     // [N,134]
    float* out_edge = out_node + (size_t)N * D_NODEREP;  // [E,128]

    {
        int total4 = N * (D_IN / 4);
        zero_kernel<<<(total4 + 255) / 256, 256>>>(N);
    }
    {
        agg_kernel<<<(E + 7) / 8, 256>>>(edge_attr, mask, edge_index, E);
    }
    {
        const int smem = NP_SMEM_FLOATS * (int)sizeof(float);
        cudaFuncSetAttribute(nodeproj_kernel, cudaFuncAttributeMaxDynamicSharedMemorySize, smem);
        int blocks = (N + TILE_N - 1) / TILE_N;
        nodeproj_kernel<<<blocks, NPTHREADS, smem>>>(x, We, out_node, N);
    }
    {
        const int smem = E_SMEM_FLOATS * (int)sizeof(float);
        cudaFuncSetAttribute(edge_kernel, cudaFuncAttributeMaxDynamicSharedMemorySize, smem);
        int blocks = (E + TILE_E - 1) / TILE_E;
        edge_kernel<<<blocks, ETHREADS, smem>>>(edge_attr, edge_index,
                                                We, bE, W1, b1, W2, b2,
                                                g1, be1, g2, be2, out_edge, E);
    }
}

// round 12
// speedup vs baseline: 1.0318x; 1.0318x over previous
#include <cuda_runtime.h>
#include <cuda_bf16.h>
#include <cstdint>

// ---------------------------------------------------------------------------
// Problem constants
// ---------------------------------------------------------------------------
#define MAXN 50000
#define D_IN 128
#define D_OUT 128
#define D_NODEREP 134  // 128 + 6
#define DH 256
#define EPS 1e-5f

#define TILE_E 64
#define ETHREADS 256

// smem strides (floats) — conflict-free mma fragment LDS
#define S_H 132        // mod 32 = 4
#define S_WA 136       // 128-col weight chunks (mod 32 = 8)
#define S_WB 264       // 256-col weight chunks (mod 32 = 8)

// ---- edge kernel smem layout (floats) ----
#define HBUF_OFF 0
#define HBUF_FLOATS (TILE_E * S_H)             // 8448
#define TZ_OFF HBUF_FLOATS                     // featz / t-half overlay
#define TZ_FLOATS (TILE_E * S_H)               // 8448
#define WB_OFF (TZ_OFF + TZ_FLOATS)            // 16896
#define WB_SLOT 2176                           // 16 rows * 136
#define E_SMEM_FLOATS (WB_OFF + 4 * WB_SLOT)   // 25600 floats = 102.4 KB

// ---- node projection kernel ----
#define TILE_N 64
#define NPTHREADS 256
#define KPAD_P 144     // 134 padded to 16*9
#define NCH_P 9
#define S_P 164        // mod 32 = 4
#define NP_A_FLOATS (TILE_N * S_P)             // 10496
#define NP_WBUF 4224                           // 16 * 264
#define NP_SMEM_FLOATS (NP_A_FLOATS + 2 * NP_WBUF)  // 18944 floats = 75.8 KB

// Scratch (static device globals: no allocation allowed)
__device__ float g_agg[(size_t)MAXN * D_IN];
__device__ float g_den[MAXN];
__device__ float g_P[(size_t)MAXN * 256];      // [N][Pa(128) | Pb(128)]

// ---------------------------------------------------------------------------
// helpers
// ---------------------------------------------------------------------------
__device__ __forceinline__ unsigned f2tf(float f) {
    unsigned u;
    asm("cvt.rna.tf32.f32 %0, %1;" : "=r"(u) : "f"(f));
    return u;
}

__device__ __forceinline__ void mma_tf32(float* c, const unsigned* a,
                                         unsigned b0, unsigned b1) {
    asm volatile(
        "mma.sync.aligned.m16n8k8.row.col.f32.tf32.tf32.f32 "
        "{%0,%1,%2,%3},{%4,%5,%6,%7},{%8,%9},{%0,%1,%2,%3};\n"
        : "+f"(c[0]), "+f"(c[1]), "+f"(c[2]), "+f"(c[3])
        : "r"(a[0]), "r"(a[1]), "r"(a[2]), "r"(a[3]), "r"(b0), "r"(b1));
}

__device__ __forceinline__ void cp16(float* dst_smem, const float* src, bool pred) {
    unsigned d = (unsigned)__cvta_generic_to_shared(dst_smem);
    int sz = pred ? 16 : 0;
    asm volatile("cp.async.cg.shared.global [%0], [%1], 16, %2;\n"
                 :: "r"(d), "l"(src), "r"(sz));
}
__device__ __forceinline__ void cp_commit() {
    asm volatile("cp.async.commit_group;\n");
}
template <int N>
__device__ __forceinline__ void cp_wait() {
    asm volatile("cp.async.wait_group %0;\n" :: "n"(N));
}

// ---------------------------------------------------------------------------
// Kernel 1: zero the scratch (float4)
// ---------------------------------------------------------------------------
__global__ void zero_kernel(int N) {
    int idx = blockIdx.x * blockDim.x + threadIdx.x;
    int total4 = N * (D_IN / 4);
    if (idx < total4) ((float4*)g_agg)[idx] = make_float4(0.f, 0.f, 0.f, 0.f);
    if (idx < N) g_den[idx] = 0.f;
}

// ---------------------------------------------------------------------------
// Kernel 2: masked scatter-add aggregation (warp per edge, float4 atomics)
// ---------------------------------------------------------------------------
__global__ void agg_kernel(const float* __restrict__ edge_attr,
                           const float* __restrict__ mask,
                           const int* __restrict__ edge_index, int E) {
    int w = (blockIdx.x * blockDim.x + threadIdx.x) >> 5;
    int lane = threadIdx.x & 31;
    if (w >= E) return;
    float m = mask[w];
    if (m == 0.f) return;
    int col = edge_index[E + w];
    const float4* a = (const float4*)(edge_attr + (size_t)w * D_IN);
    float4* dst = (float4*)(g_agg + (size_t)col * D_IN);
    float4 v = a[lane];
    v.x *= m; v.y *= m; v.z *= m; v.w *= m;
    atomicAdd(dst + lane, v);
    if (lane == 0) atomicAdd(g_den + col, m);
}

// ---------------------------------------------------------------------------
// Kernel 3: node projection  P = node_rep @ [We_a | We_b]   (N x 256)
// Also materializes node_rep into out_node.  3 blocks/SM.
// ---------------------------------------------------------------------------
__global__ void __launch_bounds__(NPTHREADS, 3)
nodeproj_kernel(const float* __restrict__ x,
                const float* __restrict__ We,
                float* __restrict__ out_node, int N) {
    extern __shared__ float sm[];
    float* A = sm;
    float* wb = sm + NP_A_FLOATS;
    __shared__ float rden_s[TILE_N];

    const int tid = threadIdx.x;
    const int lane = tid & 31;
    const int wid = tid >> 5;
    const int n0blk = blockIdx.x * TILE_N;

    const int m0 = 16 * (wid >> 1);
    const int n0 = 128 * (wid & 1);
    const int r0 = lane >> 2;
    const int qk = lane & 3;
    const int cb = 2 * qk;

    auto issue_w = [&](int ch, int stage) {  // 16 rows x 256 cols (Wea|Web)
        float* dst = wb + stage * NP_WBUF;
        int kb = ch * 16;
#pragma unroll
        for (int j = 0; j < 4; j++) {
            int i = tid + j * NPTHREADS;
            int r = i >> 6;
            int c4 = (i & 63) * 4;
            int k = kb + r;
            const float* src = (c4 < 128)
                ? We + (size_t)k * D_OUT + c4
                : We + (size_t)(D_NODEREP + k) * D_OUT + (c4 - 128);
            cp16(dst + r * S_WB + c4, src, k < D_NODEREP);
        }
        cp_commit();
    };

    issue_w(0, 0);

    if (tid < TILE_N) {
        int n = n0blk + tid;
        float d = (n < N) ? g_den[n] : 0.f;
        rden_s[tid] = 1.0f / (d + 1.0f);
    }
    __syncthreads();

    for (int idx = tid; idx < TILE_N * KPAD_P; idx += NPTHREADS) {
        int e = idx / KPAD_P;
        int k = idx - e * KPAD_P;
        int n = n0blk + e;
        float v = 0.f;
        if (n < N && k < D_NODEREP) {
            if (k < D_IN)
                v = g_agg[(size_t)n * D_IN + k] * rden_s[e];
            else
                v = x[n * 6 + (k - D_IN)];
            out_node[(size_t)n * D_NODEREP + k] = v;
        }
        A[e * S_P + k] = v;
    }

    float acc[16][4];
#pragma unroll
    for (int nt = 0; nt < 16; nt++)
#pragma unroll
        for (int q = 0; q < 4; q++) acc[nt][q] = 0.f;

    for (int ch = 0; ch < NCH_P; ch++) {
        cp_wait<0>();
        __syncthreads();
        if (ch + 1 < NCH_P) issue_w(ch + 1, (ch + 1) & 1);
        const float* cur = wb + (ch & 1) * NP_WBUF;
#pragma unroll
        for (int ks = 0; ks < 2; ks++) {
            int k0 = ch * 16 + ks * 8;
            const float* ap = A + (m0 + r0) * S_P + k0 + qk;
            unsigned a[4];
            a[0] = f2tf(ap[0]);
            a[1] = f2tf(ap[8 * S_P]);
            a[2] = f2tf(ap[4]);
            a[3] = f2tf(ap[8 * S_P + 4]);
#pragma unroll
            for (int nt = 0; nt < 16; nt++) {
                const float* bp = cur + (ks * 8 + qk) * S_WB + n0 + 8 * nt + r0;
                mma_tf32(acc[nt], a, __float_as_uint(bp[0]),
                         __float_as_uint(bp[4 * S_WB]));
            }
        }
    }

#pragma unroll
    for (int nt = 0; nt < 16; nt++) {
        int col = n0 + 8 * nt + cb;
#pragma unroll
        for (int q = 0; q < 4; q++) {
            int rr = m0 + r0 + (q >> 1) * 8;
            int cc = col + (q & 1);
            int n = n0blk + rr;
            if (n < N) g_P[(size_t)n * 256 + cc] = acc[nt][q];
        }
    }
}

// ---------------------------------------------------------------------------
// Kernel 4: fused edge MLP with register-resident fused LayerNorms.
// 64 edges/block, 256 threads (8 warps, warp tile m32 x n32), 2 blocks/SM.
// Weight ring: 4 slots x 16 rows, depth-3 cp.async prefetch.
// Race-free ordering: wait -> barrier -> compute(ch) -> issue(ch+3).
// (Round-10 configuration — measured optimum of the mma.sync design.)
// ---------------------------------------------------------------------------
__global__ void __launch_bounds__(ETHREADS, 2)
edge_kernel(const float* __restrict__ edge_attr,
            const int* __restrict__ edge_index,
            const float* __restrict__ We, const float* __restrict__ bE,
            const float* __restrict__ W1, const float* __restrict__ b1,
            const float* __restrict__ W2, const float* __restrict__ b2,
            const float* __restrict__ g1, const float* __restrict__ be1,
            const float* __restrict__ g2, const float* __restrict__ be2,
            float* __restrict__ out, int E) {
    extern __shared__ float sm[];
    float* hbuf = sm + HBUF_OFF;
    float* tz = sm + TZ_OFF;    // featz -> t-half overlay
    float* wb = sm + WB_OFF;
    __shared__ int rows_s[TILE_E], cols_s[TILE_E];
    __shared__ float red_s[TILE_E][4];    // per-row per-n-warp partial sums
    __shared__ float red_s2[TILE_E][4];
    __shared__ float mu_s[TILE_E], rinv_s[TILE_E];

    const int tid = threadIdx.x;
    const int lane = tid & 31;
    const int wid = tid >> 5;
    const int e0 = blockIdx.x * TILE_E;

    const int m0 = 32 * (wid & 1);     // 0 or 32
    const int warp_n = wid >> 1;       // 0..3
    const int n032 = 32 * warp_n;
    const int r0 = lane >> 2;
    const int qk = lane & 3;
    const int cb = 2 * qk;

    auto issue_wec = [&](int ch, int slot) {  // We_c rows 268+16ch..
        float* dst = wb + slot * WB_SLOT;
        int kb = ch * 16;
#pragma unroll
        for (int j = 0; j < 2; j++) {
            int i = tid + j * ETHREADS;
            int r = i >> 5, c4 = (i & 31) * 4;
            cp16(dst + r * S_WA + c4,
                 We + (size_t)(2 * D_NODEREP + kb + r) * D_OUT + c4, true);
        }
        cp_commit();
    };
    auto issue_w1h = [&](int hf, int ch, int slot) {  // W1 16 x 128 (col half)
        float* dst = wb + slot * WB_SLOT;
        int kb = ch * 16;
#pragma unroll
        for (int j = 0; j < 2; j++) {
            int i = tid + j * ETHREADS;
            int r = i >> 5, c4 = (i & 31) * 4;
            cp16(dst + r * S_WA + c4,
                 W1 + (size_t)(kb + r) * DH + hf * 128 + c4, true);
        }
        cp_commit();
    };
    auto issue_w2h = [&](int hf, int ch, int slot) {  // W2 16 x 128 (row half)
        float* dst = wb + slot * WB_SLOT;
        int kb = hf * 128 + ch * 16;
#pragma unroll
        for (int j = 0; j < 2; j++) {
            int i = tid + j * ETHREADS;
            int r = i >> 5, c4 = (i & 31) * 4;
            cp16(dst + r * S_WA + c4, W2 + (size_t)(kb + r) * D_OUT + c4, true);
        }
        cp_commit();
    };

    if (tid < TILE_E) {
        int eg = e0 + tid;
        rows_s[tid] = (eg < E) ? edge_index[eg] : 0;
        cols_s[tid] = (eg < E) ? edge_index[E + eg] : 0;
    }

    // GEMM1 prologue (depth 3) — overlaps the gathers below
    issue_wec(0, 0);
    issue_wec(1, 1);
    issue_wec(2, 2);

    // edge_attr tile -> tz (featz), float4 coalesced, PRE-ROUNDED to tf32
    for (int idx = tid; idx < TILE_E * 32; idx += ETHREADS) {
        int e = idx >> 5;
        int c4 = (idx & 31) * 4;
        int eg = e0 + e;
        float4 v = make_float4(0.f, 0.f, 0.f, 0.f);
        if (eg < E) v = *(const float4*)(edge_attr + (size_t)eg * D_IN + c4);
        v.x = __uint_as_float(f2tf(v.x));
        v.y = __uint_as_float(f2tf(v.y));
        v.z = __uint_as_float(f2tf(v.z));
        v.w = __uint_as_float(f2tf(v.w));
        *(float4*)(tz + e * S_H + c4) = v;
    }
    __syncthreads();  // rows_s/cols_s ready

    // hbuf = Pa[row] + Pb[col]  (float4 gather from L2-resident P, fp32)
    for (int idx = tid; idx < TILE_E * 32; idx += ETHREADS) {
        int e = idx >> 5;
        int c4 = (idx & 31) * 4;
        float4 pa = *(const float4*)(g_P + (size_t)rows_s[e] * 256 + c4);
        float4 pb = *(const float4*)(g_P + (size_t)cols_s[e] * 256 + 128 + c4);
        pa.x += pb.x; pa.y += pb.y; pa.z += pb.z; pa.w += pb.w;
        *(float4*)(hbuf + e * S_H + c4) = pa;
    }

    // ================= GEMM1: featz[64,128] @ We_c[128,128] ==============
    float acc1[2][4][4];
#pragma unroll
    for (int mt = 0; mt < 2; mt++)
#pragma unroll
        for (int nt = 0; nt < 4; nt++)
#pragma unroll
            for (int q = 0; q < 4; q++) acc1[mt][nt][q] = 0.f;

    {
        const int NCH = 8;
        for (int ch = 0; ch < NCH; ch++) {
            if (ch < NCH - 2) cp_wait<2>();
            else if (ch == NCH - 2) cp_wait<1>();
            else cp_wait<0>();
            __syncthreads();
            const float* cur = wb + (ch & 3) * WB_SLOT;
#pragma unroll
            for (int ks = 0; ks < 2; ks++) {
                int k0 = ch * 16 + ks * 8;
                unsigned a[2][4];
#pragma unroll
                for (int mt = 0; mt < 2; mt++) {
                    const float* ap = tz + (m0 + 16 * mt + r0) * S_H + k0 + qk;
                    a[mt][0] = __float_as_uint(ap[0]);
                    a[mt][1] = __float_as_uint(ap[8 * S_H]);
                    a[mt][2] = __float_as_uint(ap[4]);
                    a[mt][3] = __float_as_uint(ap[8 * S_H + 4]);
                }
#pragma unroll
                for (int nt = 0; nt < 4; nt++) {
                    const float* bp = cur + (ks * 8 + qk) * S_WA + n032 + 8 * nt + r0;
                    unsigned b0 = __float_as_uint(bp[0]);
                    unsigned b1w = __float_as_uint(bp[4 * S_WA]);
                    mma_tf32(acc1[0][nt], a[0], b0, b1w);
                    mma_tf32(acc1[1][nt], a[1], b0, b1w);
                }
            }
            if (ch + 3 < NCH) issue_wec(ch + 3, (ch + 3) & 3);
        }
    }

    // GEMM2(hf=0) prologue — slots 0,1,2 last read at ch 4,5,6 (all done)
    issue_w1h(0, 0, 0);
    issue_w1h(0, 1, 1);
    issue_w1h(0, 2, 2);

    // ---- GEMM1 epilogue with fused LN1 (register-resident) ----
#pragma unroll
    for (int mt = 0; mt < 2; mt++)
#pragma unroll
        for (int nt = 0; nt < 4; nt++) {
            int col = n032 + 8 * nt + cb;
            float2 bev = *(const float2*)(bE + col);
#pragma unroll
            for (int rh = 0; rh < 2; rh++) {
                int rr = m0 + 16 * mt + r0 + 8 * rh;
                float2 fz = *(float2*)(tz + rr * S_H + col);
                float2 pv = *(float2*)(hbuf + rr * S_H + col);
                acc1[mt][nt][2 * rh + 0] += bev.x + fz.x + pv.x;
                acc1[mt][nt][2 * rh + 1] += bev.y + fz.y + pv.y;
            }
        }
#pragma unroll
    for (int mt = 0; mt < 2; mt++)
#pragma unroll
        for (int rh = 0; rh < 2; rh++) {
            float s = 0.f, s2 = 0.f;
#pragma unroll
            for (int nt = 0; nt < 4; nt++)
#pragma unroll
                for (int b = 0; b < 2; b++) {
                    float v = acc1[mt][nt][2 * rh + b];
                    s += v; s2 += v * v;
                }
            s += __shfl_xor_sync(0xFFFFFFFF, s, 1);
            s += __shfl_xor_sync(0xFFFFFFFF, s, 2);
            s2 += __shfl_xor_sync(0xFFFFFFFF, s2, 1);
            s2 += __shfl_xor_sync(0xFFFFFFFF, s2, 2);
            if (qk == 0) {
                int rr = m0 + 16 * mt + r0 + 8 * rh;
                red_s[rr][warp_n] = s;
                red_s2[rr][warp_n] = s2;
            }
        }
    __syncthreads();
    if (tid < TILE_E) {
        float s = red_s[tid][0] + red_s[tid][1] + red_s[tid][2] + red_s[tid][3];
        float s2 = red_s2[tid][0] + red_s2[tid][1] + red_s2[tid][2] + red_s2[tid][3];
        float mu = s * (1.f / 128.f);
        float var = s2 * (1.f / 128.f) - mu * mu;
        mu_s[tid] = mu;
        rinv_s[tid] = rsqrtf(var + EPS);
    }
    __syncthreads();
    // normalize from regs, store h (tf32-rounded) to hbuf as float2
#pragma unroll
    for (int mt = 0; mt < 2; mt++)
#pragma unroll
        for (int nt = 0; nt < 4; nt++) {
            int col = n032 + 8 * nt + cb;
            float2 gv = *(const float2*)(g1 + col);
            float2 bv = *(const float2*)(be1 + col);
#pragma unroll
            for (int rh = 0; rh < 2; rh++) {
                int rr = m0 + 16 * mt + r0 + 8 * rh;
                float mu = mu_s[rr], ri = rinv_s[rr];
                float h0 = (acc1[mt][nt][2 * rh + 0] - mu) * ri * gv.x + bv.x;
                float h1 = (acc1[mt][nt][2 * rh + 1] - mu) * ri * gv.y + bv.y;
                float2 hv;
                hv.x = __uint_as_float(f2tf(h0));
                hv.y = __uint_as_float(f2tf(h1));
                *(float2*)(hbuf + rr * S_H + col) = hv;
            }
        }

    // ============ GEMM2+GEMM3 in two 128-halves, acc3 persistent =========
    float acc3[2][4][4];
#pragma unroll
    for (int mt = 0; mt < 2; mt++)
#pragma unroll
        for (int nt = 0; nt < 4; nt++)
#pragma unroll
            for (int q = 0; q < 4; q++) acc3[mt][nt][q] = 0.f;

#pragma unroll 1
    for (int hf = 0; hf < 2; hf++) {
        // ---- GEMM2 half: t_half = relu(h @ W1[:, hf*128:+128] + b1h) ----
        {
            float acc2[2][4][4];
#pragma unroll
            for (int mt = 0; mt < 2; mt++)
#pragma unroll
                for (int nt = 0; nt < 4; nt++)
#pragma unroll
                    for (int q = 0; q < 4; q++) acc2[mt][nt][q] = 0.f;

            if (hf) {  // hf=0 prologue hoisted before LN1
                issue_w1h(hf, 0, 0);
                issue_w1h(hf, 1, 1);
                issue_w1h(hf, 2, 2);
            }
            const int NCH = 8;
            for (int ch = 0; ch < NCH; ch++) {
                if (ch < NCH - 2) cp_wait<2>();
                else if (ch == NCH - 2) cp_wait<1>();
                else cp_wait<0>();
                __syncthreads();
                const float* cur = wb + (ch & 3) * WB_SLOT;
#pragma unroll
                for (int ks = 0; ks < 2; ks++) {
                    int k0 = ch * 16 + ks * 8;
                    unsigned a[2][4];
#pragma unroll
                    for (int mt = 0; mt < 2; mt++) {
                        const float* ap = hbuf + (m0 + 16 * mt + r0) * S_H + k0 + qk;
                        a[mt][0] = __float_as_uint(ap[0]);
                        a[mt][1] = __float_as_uint(ap[8 * S_H]);
                        a[mt][2] = __float_as_uint(ap[4]);
                        a[mt][3] = __float_as_uint(ap[8 * S_H + 4]);
                    }
#pragma unroll
                    for (int nt = 0; nt < 4; nt++) {
                        const float* bp = cur + (ks * 8 + qk) * S_WA + n032 + 8 * nt + r0;
                        unsigned b0 = __float_as_uint(bp[0]);
                        unsigned b1w = __float_as_uint(bp[4 * S_WA]);
                        mma_tf32(acc2[0][nt], a[0], b0, b1w);
                        mma_tf32(acc2[1][nt], a[1], b0, b1w);
                    }
                }
                if (ch + 3 < NCH) issue_w1h(hf, ch + 3, (ch + 3) & 3);
            }
            __syncthreads();  // ring reads done; tz free to write

            // hoist GEMM3 prologue — copies land during t-store
            issue_w2h(hf, 0, 0);
            issue_w2h(hf, 1, 1);
            issue_w2h(hf, 2, 2);

            // t_half -> tz (tf32-rounded bits, GEMM3 A operand), float2
#pragma unroll
            for (int mt = 0; mt < 2; mt++)
#pragma unroll
                for (int nt = 0; nt < 4; nt++) {
                    int col = n032 + 8 * nt + cb;
                    float2 b1v = *(const float2*)(b1 + hf * 128 + col);
#pragma unroll
                    for (int rh = 0; rh < 2; rh++) {
                        int rr = m0 + 16 * mt + r0 + 8 * rh;
                        float t0 = fmaxf(acc2[mt][nt][2 * rh + 0] + b1v.x, 0.f);
                        float t1 = fmaxf(acc2[mt][nt][2 * rh + 1] + b1v.y, 0.f);
                        float2 tv;
                        tv.x = __uint_as_float(f2tf(t0));
                        tv.y = __uint_as_float(f2tf(t1));
                        *(float2*)(tz + rr * S_H + col) = tv;
                    }
                }
        }
        __syncthreads();

        // ---- GEMM3 half: acc3 += t_half @ W2[hf*128:+128, :] ----
        {
            const int NCH = 8;
            for (int ch = 0; ch < NCH; ch++) {
                if (ch < NCH - 2) cp_wait<2>();
                else if (ch == NCH - 2) cp_wait<1>();
                else cp_wait<0>();
                __syncthreads();
                const float* cur = wb + (ch & 3) * WB_SLOT;
#pragma unroll
                for (int ks = 0; ks < 2; ks++) {
                    int k0 = ch * 16 + ks * 8;
                    unsigned a[2][4];
#pragma unroll
                    for (int mt = 0; mt < 2; mt++) {
                        const float* ap = tz + (m0 + 16 * mt + r0) * S_H + k0 + qk;
                        a[mt][0] = __float_as_uint(ap[0]);
                        a[mt][1] = __float_as_uint(ap[8 * S_H]);
                        a[mt][2] = __float_as_uint(ap[4]);
                        a[mt][3] = __float_as_uint(ap[8 * S_H + 4]);
                    }
#pragma unroll
                    for (int nt = 0; nt < 4; nt++) {
                        const float* bp = cur + (ks * 8 + qk) * S_WA + n032 + 8 * nt + r0;
                        unsigned b0 = __float_as_uint(bp[0]);
                        unsigned b1w = __float_as_uint(bp[4 * S_WA]);
                        mma_tf32(acc3[0][nt], a[0], b0, b1w);
                        mma_tf32(acc3[1][nt], a[1], b0, b1w);
                    }
                }
                if (ch + 3 < NCH) issue_w2h(hf, ch + 3, (ch + 3) & 3);
            }
        }
        __syncthreads();  // tz reads done before next hf overwrites it
    }

    // ---- GEMM3 epilogue with fused LN2 (register-resident) -> global ----
    // z = acc3 + b2 + h(hbuf)
#pragma unroll
    for (int mt = 0; mt < 2; mt++)
#pragma unroll
        for (int nt = 0; nt < 4; nt++) {
            int col = n032 + 8 * nt + cb;
            float2 b2v = *(const float2*)(b2 + col);
#pragma unroll
            for (int rh = 0; rh < 2; rh++) {
                int rr = m0 + 16 * mt + r0 + 8 * rh;
                float2 hv = *(float2*)(hbuf + rr * S_H + col);
                acc3[mt][nt][2 * rh + 0] += b2v.x + hv.x;
                acc3[mt][nt][2 * rh + 1] += b2v.y + hv.y;
            }
        }
#pragma unroll
    for (int mt = 0; mt < 2; mt++)
#pragma unroll
        for (int rh = 0; rh < 2; rh++) {
            float s = 0.f, s2 = 0.f;
#pragma unroll
            for (int nt = 0; nt < 4; nt++)
#pragma unroll
                for (int b = 0; b < 2; b++) {
                    float v = acc3[mt][nt][2 * rh + b];
                    s += v; s2 += v * v;
                }
            s += __shfl_xor_sync(0xFFFFFFFF, s, 1);
            s += __shfl_xor_sync(0xFFFFFFFF, s, 2);
            s2 += __shfl_xor_sync(0xFFFFFFFF, s2, 1);
            s2 += __shfl_xor_sync(0xFFFFFFFF, s2, 2);
            if (qk == 0) {
                int rr = m0 + 16 * mt + r0 + 8 * rh;
                red_s[rr][warp_n] = s;
                red_s2[rr][warp_n] = s2;
            }
        }
    __syncthreads();
    if (tid < TILE_E) {
        float s = red_s[tid][0] + red_s[tid][1] + red_s[tid][2] + red_s[tid][3];
        float s2 = red_s2[tid][0] + red_s2[tid][1] + red_s2[tid][2] + red_s2[tid][3];
        float mu = s * (1.f / 128.f);
        float var = s2 * (1.f / 128.f) - mu * mu;
        mu_s[tid] = mu;
        rinv_s[tid] = rsqrtf(var + EPS);
    }
    __syncthreads();
#pragma unroll
    for (int mt = 0; mt < 2; mt++)
#pragma unroll
        for (int nt = 0; nt < 4; nt++) {
            int col = n032 + 8 * nt + cb;
            float2 gv = *(const float2*)(g2 + col);
            float2 bv = *(const float2*)(be2 + col);
#pragma unroll
            for (int rh = 0; rh < 2; rh++) {
                int rr = m0 + 16 * mt + r0 + 8 * rh;
                int eg = e0 + rr;
                if (eg < E) {
                    float mu = mu_s[rr], ri = rinv_s[rr];
                    float2 ov;
                    ov.x = (acc3[mt][nt][2 * rh + 0] - mu) * ri * gv.x + bv.x;
                    ov.y = (acc3[mt][nt][2 * rh + 1] - mu) * ri * gv.y + bv.y;
                    *(float2*)(out + (size_t)eg * D_OUT + col) = ov;
                }
            }
        }
}

// ---------------------------------------------------------------------------
// launch
// ---------------------------------------------------------------------------
extern "C" void kernel_launch(void* const* d_in, const int* in_sizes, int n_in,
                              void* d_out, int out_size) {
    const void* p[16];
    int sz[16];
    int m = 0;
    for (int i = 0; i < n_in && m < 16; i++) {
        if (in_sizes[i] == 1) continue;
        p[m] = d_in[i];
        sz[m] = in_sizes[i];
        m++;
    }
    const float* x          = (const float*)p[0];
    const int*   edge_index = (const int*)p[1];
    const float* edge_attr  = (const float*)p[2];
    const float* mask       = (const float*)p[3];
    const float* We         = (const float*)p[4];
    const float* bE         = (const float*)p[5];
    const float* W1         = (const float*)p[6];
    const float* b1         = (const float*)p[7];
    const float* W2         = (const float*)p[8];
    const float* b2         = (const float*)p[9];
    const float* g1         = (const float*)p[10];
    const float* be1        = (const float*)p[11];
    const float* g2         = (const float*)p[12];
    const float* be2        = (const float*)p[13];

    const int N = sz[0] / 6;
    const int E = sz[3];

    float* out_node = (float*)d_out;                     // [N,134]
    float* out_edge = out_node + (size_t)N * D_NODEREP;  // [E,128]

    {
        int total4 = N * (D_IN / 4);
        zero_kernel<<<(total4 + 255) / 256, 256>>>(N);
    }
    {
        agg_kernel<<<(E + 7) / 8, 256>>>(edge_attr, mask, edge_index, E);
    }
    {
        const int smem = NP_SMEM_FLOATS * (int)sizeof(float);
        cudaFuncSetAttribute(nodeproj_kernel, cudaFuncAttributeMaxDynamicSharedMemorySize, smem);
        int blocks = (N + TILE_N - 1) / TILE_N;
        nodeproj_kernel<<<blocks, NPTHREADS, smem>>>(x, We, out_node, N);
    }
    {
        const int smem = E_SMEM_FLOATS * (int)sizeof(float);
        cudaFuncSetAttribute(edge_kernel, cudaFuncAttributeMaxDynamicSharedMemorySize, smem);
        int blocks = (E + TILE_E - 1) / TILE_E;
        edge_kernel<<<blocks, ETHREADS, smem>>>(edge_attr, edge_index,
                                                We, bE, W1, b1, W2, b2,
                                                g1, be1, g2, be2, out_edge, E);
    }
}

// round 14
// speedup vs baseline: 1.0324x; 1.0005x over previous
#include <cuda_runtime.h>
#include <cuda_bf16.h>
#include <cstdint>

// ---------------------------------------------------------------------------
// Problem constants
// ---------------------------------------------------------------------------
#define MAXN 50000
#define D_IN 128
#define D_OUT 128
#define D_NODEREP 134  // 128 + 6
#define DH 256
#define EPS 1e-5f

#define TILE_E 64
#define ETHREADS 256

// smem strides (floats) — conflict-free mma fragment LDS
#define S_H 132        // mod 32 = 4
#define S_WA 136       // 128-col weight chunks (mod 32 = 8)
#define S_WB 264       // 256-col weight chunks (mod 32 = 8)

// ---- edge kernel smem layout (floats) ----
#define HBUF_OFF 0
#define HBUF_FLOATS (TILE_E * S_H)             // 8448
#define TZ_OFF HBUF_FLOATS                     // featz / t-half overlay
#define TZ_FLOATS (TILE_E * S_H)               // 8448
#define WB_OFF (TZ_OFF + TZ_FLOATS)            // 16896
#define WB_SLOT 2176                           // 16 rows * 136
#define E_SMEM_FLOATS (WB_OFF + 4 * WB_SLOT)   // 25600 floats = 102.4 KB

// ---- node projection kernel ----
#define TILE_N 64
#define NPTHREADS 256
#define KPAD_P 144     // 134 padded to 8*18
#define NCH_P 18       // 18 chunks of 8 k-rows
#define S_P 164        // mod 32 = 4
#define NP_A_FLOATS (TILE_N * S_P)             // 10496
#define NP_WSLOT 2112                          // 8 rows * 264
#define NP_SMEM_FLOATS (NP_A_FLOATS + 4 * NP_WSLOT)  // 18944 floats = 75.8 KB

// Scratch (static device globals: no allocation allowed)
__device__ float g_agg[(size_t)MAXN * D_IN];
__device__ float g_den[MAXN];
__device__ float g_P[(size_t)MAXN * 256];      // [N][Pa(128) | Pb(128)]

// ---------------------------------------------------------------------------
// helpers
// ---------------------------------------------------------------------------
__device__ __forceinline__ unsigned f2tf(float f) {
    unsigned u;
    asm("cvt.rna.tf32.f32 %0, %1;" : "=r"(u) : "f"(f));
    return u;
}

__device__ __forceinline__ void mma_tf32(float* c, const unsigned* a,
                                         unsigned b0, unsigned b1) {
    asm volatile(
        "mma.sync.aligned.m16n8k8.row.col.f32.tf32.tf32.f32 "
        "{%0,%1,%2,%3},{%4,%5,%6,%7},{%8,%9},{%0,%1,%2,%3};\n"
        : "+f"(c[0]), "+f"(c[1]), "+f"(c[2]), "+f"(c[3])
        : "r"(a[0]), "r"(a[1]), "r"(a[2]), "r"(a[3]), "r"(b0), "r"(b1));
}

__device__ __forceinline__ void cp16(float* dst_smem, const float* src, bool pred) {
    unsigned d = (unsigned)__cvta_generic_to_shared(dst_smem);
    int sz = pred ? 16 : 0;
    asm volatile("cp.async.cg.shared.global [%0], [%1], 16, %2;\n"
                 :: "r"(d), "l"(src), "r"(sz));
}
__device__ __forceinline__ void cp_commit() {
    asm volatile("cp.async.commit_group;\n");
}
template <int N>
__device__ __forceinline__ void cp_wait() {
    asm volatile("cp.async.wait_group %0;\n" :: "n"(N));
}

// ---------------------------------------------------------------------------
// Kernel 1: zero the scratch (float4)
// ---------------------------------------------------------------------------
__global__ void zero_kernel(int N) {
    int idx = blockIdx.x * blockDim.x + threadIdx.x;
    int total4 = N * (D_IN / 4);
    if (idx < total4) ((float4*)g_agg)[idx] = make_float4(0.f, 0.f, 0.f, 0.f);
    if (idx < N) g_den[idx] = 0.f;
}

// ---------------------------------------------------------------------------
// Kernel 2: masked scatter-add aggregation (warp per edge, float4 atomics)
// ---------------------------------------------------------------------------
__global__ void agg_kernel(const float* __restrict__ edge_attr,
                           const float* __restrict__ mask,
                           const int* __restrict__ edge_index, int E) {
    int w = (blockIdx.x * blockDim.x + threadIdx.x) >> 5;
    int lane = threadIdx.x & 31;
    if (w >= E) return;
    float m = mask[w];
    if (m == 0.f) return;
    int col = edge_index[E + w];
    const float4* a = (const float4*)(edge_attr + (size_t)w * D_IN);
    float4* dst = (float4*)(g_agg + (size_t)col * D_IN);
    float4 v = a[lane];
    v.x *= m; v.y *= m; v.z *= m; v.w *= m;
    atomicAdd(dst + lane, v);
    if (lane == 0) atomicAdd(g_den + col, m);
}

// ---------------------------------------------------------------------------
// Kernel 3: node projection  P = node_rep @ [We_a | We_b]   (N x 256)
// Also materializes node_rep into out_node.  3 blocks/SM.
// Ring: 4 slots x 8 k-rows, depth-3 prefetch (same smem as the old 2x16).
// Race-free ordering: wait -> barrier -> compute(ch) -> issue(ch+3).
// ---------------------------------------------------------------------------
__global__ void __launch_bounds__(NPTHREADS, 3)
nodeproj_kernel(const float* __restrict__ x,
                const float* __restrict__ We,
                float* __restrict__ out_node, int N) {
    extern __shared__ float sm[];
    float* A = sm;
    float* wb = sm + NP_A_FLOATS;
    __shared__ float rden_s[TILE_N];

    const int tid = threadIdx.x;
    const int lane = tid & 31;
    const int wid = tid >> 5;
    const int n0blk = blockIdx.x * TILE_N;

    const int m0 = 16 * (wid >> 1);
    const int n0 = 128 * (wid & 1);
    const int r0 = lane >> 2;
    const int qk = lane & 3;
    const int cb = 2 * qk;

    auto issue_w = [&](int ch, int slot) {  // 8 rows x 256 cols (Wea|Web)
        float* dst = wb + slot * NP_WSLOT;
        int kb = ch * 8;
#pragma unroll
        for (int j = 0; j < 2; j++) {
            int i = tid + j * NPTHREADS;
            int r = i >> 6;                 // 0..7
            int c4 = (i & 63) * 4;
            int k = kb + r;
            const float* src = (c4 < 128)
                ? We + (size_t)k * D_OUT + c4
                : We + (size_t)(D_NODEREP + k) * D_OUT + (c4 - 128);
            cp16(dst + r * S_WB + c4, src, k < D_NODEREP);
        }
        cp_commit();
    };

    // depth-3 prologue — copies land while A is staged below
    issue_w(0, 0);
    issue_w(1, 1);
    issue_w(2, 2);

    if (tid < TILE_N) {
        int n = n0blk + tid;
        float d = (n < N) ? g_den[n] : 0.f;
        rden_s[tid] = 1.0f / (d + 1.0f);
    }
    __syncthreads();

    for (int idx = tid; idx < TILE_N * KPAD_P; idx += NPTHREADS) {
        int e = idx / KPAD_P;
        int k = idx - e * KPAD_P;
        int n = n0blk + e;
        float v = 0.f;
        if (n < N && k < D_NODEREP) {
            if (k < D_IN)
                v = g_agg[(size_t)n * D_IN + k] * rden_s[e];
            else
                v = x[n * 6 + (k - D_IN)];
            out_node[(size_t)n * D_NODEREP + k] = v;
        }
        A[e * S_P + k] = v;
    }

    float acc[16][4];
#pragma unroll
    for (int nt = 0; nt < 16; nt++)
#pragma unroll
        for (int q = 0; q < 4; q++) acc[nt][q] = 0.f;

    for (int ch = 0; ch < NCH_P; ch++) {
        if (ch < NCH_P - 2) cp_wait<2>();
        else if (ch == NCH_P - 2) cp_wait<1>();
        else cp_wait<0>();
        __syncthreads();
        const float* cur = wb + (ch & 3) * NP_WSLOT;
        int k0 = ch * 8;
        const float* ap = A + (m0 + r0) * S_P + k0 + qk;
        unsigned a[4];
        a[0] = f2tf(ap[0]);
        a[1] = f2tf(ap[8 * S_P]);
        a[2] = f2tf(ap[4]);
        a[3] = f2tf(ap[8 * S_P + 4]);
#pragma unroll
        for (int nt = 0; nt < 16; nt++) {
            const float* bp = cur + qk * S_WB + n0 + 8 * nt + r0;
            mma_tf32(acc[nt], a, __float_as_uint(bp[0]),
                     __float_as_uint(bp[4 * S_WB]));
        }
        if (ch + 3 < NCH_P) issue_w(ch + 3, (ch + 3) & 3);
    }

#pragma unroll
    for (int nt = 0; nt < 16; nt++) {
        int col = n0 + 8 * nt + cb;
#pragma unroll
        for (int q = 0; q < 4; q++) {
            int rr = m0 + r0 + (q >> 1) * 8;
            int cc = col + (q & 1);
            int n = n0blk + rr;
            if (n < N) g_P[(size_t)n * 256 + cc] = acc[nt][q];
        }
    }
}

// ---------------------------------------------------------------------------
// Kernel 4: fused edge MLP with register-resident fused LayerNorms.
// 64 edges/block, 256 threads (8 warps, warp tile m32 x n32), 2 blocks/SM.
// Weight ring: 4 slots x 16 rows, depth-3 cp.async prefetch.
// Race-free ordering: wait -> barrier -> compute(ch) -> issue(ch+3).
// (Round-12 configuration — measured optimum of the mma.sync design. DO NOT PERTURB.)
// ---------------------------------------------------------------------------
__global__ void __launch_bounds__(ETHREADS, 2)
edge_kernel(const float* __restrict__ edge_attr,
            const int* __restrict__ edge_index,
            const float* __restrict__ We, const float* __restrict__ bE,
            const float* __restrict__ W1, const float* __restrict__ b1,
            const float* __restrict__ W2, const float* __restrict__ b2,
            const float* __restrict__ g1, const float* __restrict__ be1,
            const float* __restrict__ g2, const float* __restrict__ be2,
            float* __restrict__ out, int E) {
    extern __shared__ float sm[];
    float* hbuf = sm + HBUF_OFF;
    float* tz = sm + TZ_OFF;    // featz -> t-half overlay
    float* wb = sm + WB_OFF;
    __shared__ int rows_s[TILE_E], cols_s[TILE_E];
    __shared__ float red_s[TILE_E][4];    // per-row per-n-warp partial sums
    __shared__ float red_s2[TILE_E][4];
    __shared__ float mu_s[TILE_E], rinv_s[TILE_E];

    const int tid = threadIdx.x;
    const int lane = tid & 31;
    const int wid = tid >> 5;
    const int e0 = blockIdx.x * TILE_E;

    const int m0 = 32 * (wid & 1);     // 0 or 32
    const int warp_n = wid >> 1;       // 0..3
    const int n032 = 32 * warp_n;
    const int r0 = lane >> 2;
    const int qk = lane & 3;
    const int cb = 2 * qk;

    auto issue_wec = [&](int ch, int slot) {  // We_c rows 268+16ch..
        float* dst = wb + slot * WB_SLOT;
        int kb = ch * 16;
#pragma unroll
        for (int j = 0; j < 2; j++) {
            int i = tid + j * ETHREADS;
            int r = i >> 5, c4 = (i & 31) * 4;
            cp16(dst + r * S_WA + c4,
                 We + (size_t)(2 * D_NODEREP + kb + r) * D_OUT + c4, true);
        }
        cp_commit();
    };
    auto issue_w1h = [&](int hf, int ch, int slot) {  // W1 16 x 128 (col half)
        float* dst = wb + slot * WB_SLOT;
        int kb = ch * 16;
#pragma unroll
        for (int j = 0; j < 2; j++) {
            int i = tid + j * ETHREADS;
            int r = i >> 5, c4 = (i & 31) * 4;
            cp16(dst + r * S_WA + c4,
                 W1 + (size_t)(kb + r) * DH + hf * 128 + c4, true);
        }
        cp_commit();
    };
    auto issue_w2h = [&](int hf, int ch, int slot) {  // W2 16 x 128 (row half)
        float* dst = wb + slot * WB_SLOT;
        int kb = hf * 128 + ch * 16;
#pragma unroll
        for (int j = 0; j < 2; j++) {
            int i = tid + j * ETHREADS;
            int r = i >> 5, c4 = (i & 31) * 4;
            cp16(dst + r * S_WA + c4, W2 + (size_t)(kb + r) * D_OUT + c4, true);
        }
        cp_commit();
    };

    if (tid < TILE_E) {
        int eg = e0 + tid;
        rows_s[tid] = (eg < E) ? edge_index[eg] : 0;
        cols_s[tid] = (eg < E) ? edge_index[E + eg] : 0;
    }

    // GEMM1 prologue (depth 3) — overlaps the gathers below
    issue_wec(0, 0);
    issue_wec(1, 1);
    issue_wec(2, 2);

    // edge_attr tile -> tz (featz), float4 coalesced, PRE-ROUNDED to tf32
    for (int idx = tid; idx < TILE_E * 32; idx += ETHREADS) {
        int e = idx >> 5;
        int c4 = (idx & 31) * 4;
        int eg = e0 + e;
        float4 v = make_float4(0.f, 0.f, 0.f, 0.f);
        if (eg < E) v = *(const float4*)(edge_attr + (size_t)eg * D_IN + c4);
        v.x = __uint_as_float(f2tf(v.x));
        v.y = __uint_as_float(f2tf(v.y));
        v.z = __uint_as_float(f2tf(v.z));
        v.w = __uint_as_float(f2tf(v.w));
        *(float4*)(tz + e * S_H + c4) = v;
    }
    __syncthreads();  // rows_s/cols_s ready

    // hbuf = Pa[row] + Pb[col]  (float4 gather from L2-resident P, fp32)
    for (int idx = tid; idx < TILE_E * 32; idx += ETHREADS) {
        int e = idx >> 5;
        int c4 = (idx & 31) * 4;
        float4 pa = *(const float4*)(g_P + (size_t)rows_s[e] * 256 + c4);
        float4 pb = *(const float4*)(g_P + (size_t)cols_s[e] * 256 + 128 + c4);
        pa.x += pb.x; pa.y += pb.y; pa.z += pb.z; pa.w += pb.w;
        *(float4*)(hbuf + e * S_H + c4) = pa;
    }

    // ================= GEMM1: featz[64,128] @ We_c[128,128] ==============
    float acc1[2][4][4];
#pragma unroll
    for (int mt = 0; mt < 2; mt++)
#pragma unroll
        for (int nt = 0; nt < 4; nt++)
#pragma unroll
            for (int q = 0; q < 4; q++) acc1[mt][nt][q] = 0.f;

    {
        const int NCH = 8;
        for (int ch = 0; ch < NCH; ch++) {
            if (ch < NCH - 2) cp_wait<2>();
            else if (ch == NCH - 2) cp_wait<1>();
            else cp_wait<0>();
            __syncthreads();
            const float* cur = wb + (ch & 3) * WB_SLOT;
#pragma unroll
            for (int ks = 0; ks < 2; ks++) {
                int k0 = ch * 16 + ks * 8;
                unsigned a[2][4];
#pragma unroll
                for (int mt = 0; mt < 2; mt++) {
                    const float* ap = tz + (m0 + 16 * mt + r0) * S_H + k0 + qk;
                    a[mt][0] = __float_as_uint(ap[0]);
                    a[mt][1] = __float_as_uint(ap[8 * S_H]);
                    a[mt][2] = __float_as_uint(ap[4]);
                    a[mt][3] = __float_as_uint(ap[8 * S_H + 4]);
                }
#pragma unroll
                for (int nt = 0; nt < 4; nt++) {
                    const float* bp = cur + (ks * 8 + qk) * S_WA + n032 + 8 * nt + r0;
                    unsigned b0 = __float_as_uint(bp[0]);
                    unsigned b1w = __float_as_uint(bp[4 * S_WA]);
                    mma_tf32(acc1[0][nt], a[0], b0, b1w);
                    mma_tf32(acc1[1][nt], a[1], b0, b1w);
                }
            }
            if (ch + 3 < NCH) issue_wec(ch + 3, (ch + 3) & 3);
        }
    }

    // GEMM2(hf=0) prologue — slots 0,1,2 last read at ch 4,5,6 (all done)
    issue_w1h(0, 0, 0);
    issue_w1h(0, 1, 1);
    issue_w1h(0, 2, 2);

    // ---- GEMM1 epilogue with fused LN1 (register-resident) ----
#pragma unroll
    for (int mt = 0; mt < 2; mt++)
#pragma unroll
        for (int nt = 0; nt < 4; nt++) {
            int col = n032 + 8 * nt + cb;
            float2 bev = *(const float2*)(bE + col);
#pragma unroll
            for (int rh = 0; rh < 2; rh++) {
                int rr = m0 + 16 * mt + r0 + 8 * rh;
                float2 fz = *(float2*)(tz + rr * S_H + col);
                float2 pv = *(float2*)(hbuf + rr * S_H + col);
                acc1[mt][nt][2 * rh + 0] += bev.x + fz.x + pv.x;
                acc1[mt][nt][2 * rh + 1] += bev.y + fz.y + pv.y;
            }
        }
#pragma unroll
    for (int mt = 0; mt < 2; mt++)
#pragma unroll
        for (int rh = 0; rh < 2; rh++) {
            float s = 0.f, s2 = 0.f;
#pragma unroll
            for (int nt = 0; nt < 4; nt++)
#pragma unroll
                for (int b = 0; b < 2; b++) {
                    float v = acc1[mt][nt][2 * rh + b];
                    s += v; s2 += v * v;
                }
            s += __shfl_xor_sync(0xFFFFFFFF, s, 1);
            s += __shfl_xor_sync(0xFFFFFFFF, s, 2);
            s2 += __shfl_xor_sync(0xFFFFFFFF, s2, 1);
            s2 += __shfl_xor_sync(0xFFFFFFFF, s2, 2);
            if (qk == 0) {
                int rr = m0 + 16 * mt + r0 + 8 * rh;
                red_s[rr][warp_n] = s;
                red_s2[rr][warp_n] = s2;
            }
        }
    __syncthreads();
    if (tid < TILE_E) {
        float s = red_s[tid][0] + red_s[tid][1] + red_s[tid][2] + red_s[tid][3];
        float s2 = red_s2[tid][0] + red_s2[tid][1] + red_s2[tid][2] + red_s2[tid][3];
        float mu = s * (1.f / 128.f);
        float var = s2 * (1.f / 128.f) - mu * mu;
        mu_s[tid] = mu;
        rinv_s[tid] = rsqrtf(var + EPS);
    }
    __syncthreads();
    // normalize from regs, store h (tf32-rounded) to hbuf as float2
#pragma unroll
    for (int mt = 0; mt < 2; mt++)
#pragma unroll
        for (int nt = 0; nt < 4; nt++) {
            int col = n032 + 8 * nt + cb;
            float2 gv = *(const float2*)(g1 + col);
            float2 bv = *(const float2*)(be1 + col);
#pragma unroll
            for (int rh = 0; rh < 2; rh++) {
                int rr = m0 + 16 * mt + r0 + 8 * rh;
                float mu = mu_s[rr], ri = rinv_s[rr];
                float h0 = (acc1[mt][nt][2 * rh + 0] - mu) * ri * gv.x + bv.x;
                float h1 = (acc1[mt][nt][2 * rh + 1] - mu) * ri * gv.y + bv.y;
                float2 hv;
                hv.x = __uint_as_float(f2tf(h0));
                hv.y = __uint_as_float(f2tf(h1));
                *(float2*)(hbuf + rr * S_H + col) = hv;
            }
        }

    // ============ GEMM2+GEMM3 in two 128-halves, acc3 persistent =========
    float acc3[2][4][4];
#pragma unroll
    for (int mt = 0; mt < 2; mt++)
#pragma unroll
        for (int nt = 0; nt < 4; nt++)
#pragma unroll
            for (int q = 0; q < 4; q++) acc3[mt][nt][q] = 0.f;

#pragma unroll 1
    for (int hf = 0; hf < 2; hf++) {
        // ---- GEMM2 half: t_half = relu(h @ W1[:, hf*128:+128] + b1h) ----
        {
            float acc2[2][4][4];
#pragma unroll
            for (int mt = 0; mt < 2; mt++)
#pragma unroll
                for (int nt = 0; nt < 4; nt++)
#pragma unroll
                    for (int q = 0; q < 4; q++) acc2[mt][nt][q] = 0.f;

            if (hf) {  // hf=0 prologue hoisted before LN1
                issue_w1h(hf, 0, 0);
                issue_w1h(hf, 1, 1);
                issue_w1h(hf, 2, 2);
            }
            const int NCH = 8;
            for (int ch = 0; ch < NCH; ch++) {
                if (ch < NCH - 2) cp_wait<2>();
                else if (ch == NCH - 2) cp_wait<1>();
                else cp_wait<0>();
                __syncthreads();
                const float* cur = wb + (ch & 3) * WB_SLOT;
#pragma unroll
                for (int ks = 0; ks < 2; ks++) {
                    int k0 = ch * 16 + ks * 8;
                    unsigned a[2][4];
#pragma unroll
                    for (int mt = 0; mt < 2; mt++) {
                        const float* ap = hbuf + (m0 + 16 * mt + r0) * S_H + k0 + qk;
                        a[mt][0] = __float_as_uint(ap[0]);
                        a[mt][1] = __float_as_uint(ap[8 * S_H]);
                        a[mt][2] = __float_as_uint(ap[4]);
                        a[mt][3] = __float_as_uint(ap[8 * S_H + 4]);
                    }
#pragma unroll
                    for (int nt = 0; nt < 4; nt++) {
                        const float* bp = cur + (ks * 8 + qk) * S_WA + n032 + 8 * nt + r0;
                        unsigned b0 = __float_as_uint(bp[0]);
                        unsigned b1w = __float_as_uint(bp[4 * S_WA]);
                        mma_tf32(acc2[0][nt], a[0], b0, b1w);
                        mma_tf32(acc2[1][nt], a[1], b0, b1w);
                    }
                }
                if (ch + 3 < NCH) issue_w1h(hf, ch + 3, (ch + 3) & 3);
            }
            __syncthreads();  // ring reads done; tz free to write

            // hoist GEMM3 prologue — copies land during t-store
            issue_w2h(hf, 0, 0);
            issue_w2h(hf, 1, 1);
            issue_w2h(hf, 2, 2);

            // t_half -> tz (tf32-rounded bits, GEMM3 A operand), float2
#pragma unroll
            for (int mt = 0; mt < 2; mt++)
#pragma unroll
                for (int nt = 0; nt < 4; nt++) {
                    int col = n032 + 8 * nt + cb;
                    float2 b1v = *(const float2*)(b1 + hf * 128 + col);
#pragma unroll
                    for (int rh = 0; rh < 2; rh++) {
                        int rr = m0 + 16 * mt + r0 + 8 * rh;
                        float t0 = fmaxf(acc2[mt][nt][2 * rh + 0] + b1v.x, 0.f);
                        float t1 = fmaxf(acc2[mt][nt][2 * rh + 1] + b1v.y, 0.f);
                        float2 tv;
                        tv.x = __uint_as_float(f2tf(t0));
                        tv.y = __uint_as_float(f2tf(t1));
                        *(float2*)(tz + rr * S_H + col) = tv;
                    }
                }
        }
        __syncthreads();

        // ---- GEMM3 half: acc3 += t_half @ W2[hf*128:+128, :] ----
        {
            const int NCH = 8;
            for (int ch = 0; ch < NCH; ch++) {
                if (ch < NCH - 2) cp_wait<2>();
                else if (ch == NCH - 2) cp_wait<1>();
                else cp_wait<0>();
                __syncthreads();
                const float* cur = wb + (ch & 3) * WB_SLOT;
#pragma unroll
                for (int ks = 0; ks < 2; ks++) {
                    int k0 = ch * 16 + ks * 8;
                    unsigned a[2][4];
#pragma unroll
                    for (int mt = 0; mt < 2; mt++) {
                        const float* ap = tz + (m0 + 16 * mt + r0) * S_H + k0 + qk;
                        a[mt][0] = __float_as_uint(ap[0]);
                        a[mt][1] = __float_as_uint(ap[8 * S_H]);
                        a[mt][2] = __float_as_uint(ap[4]);
                        a[mt][3] = __float_as_uint(ap[8 * S_H + 4]);
                    }
#pragma unroll
                    for (int nt = 0; nt < 4; nt++) {
                        const float* bp = cur + (ks * 8 + qk) * S_WA + n032 + 8 * nt + r0;
                        unsigned b0 = __float_as_uint(bp[0]);
                        unsigned b1w = __float_as_uint(bp[4 * S_WA]);
                        mma_tf32(acc3[0][nt], a[0], b0, b1w);
                        mma_tf32(acc3[1][nt], a[1], b0, b1w);
                    }
                }
                if (ch + 3 < NCH) issue_w2h(hf, ch + 3, (ch + 3) & 3);
            }
        }
        __syncthreads();  // tz reads done before next hf overwrites it
    }

    // ---- GEMM3 epilogue with fused LN2 (register-resident) -> global ----
    // z = acc3 + b2 + h(hbuf)
#pragma unroll
    for (int mt = 0; mt < 2; mt++)
#pragma unroll
        for (int nt = 0; nt < 4; nt++) {
            int col = n032 + 8 * nt + cb;
            float2 b2v = *(const float2*)(b2 + col);
#pragma unroll
            for (int rh = 0; rh < 2; rh++) {
                int rr = m0 + 16 * mt + r0 + 8 * rh;
                float2 hv = *(float2*)(hbuf + rr * S_H + col);
                acc3[mt][nt][2 * rh + 0] += b2v.x + hv.x;
                acc3[mt][nt][2 * rh + 1] += b2v.y + hv.y;
            }
        }
#pragma unroll
    for (int mt = 0; mt < 2; mt++)
#pragma unroll
        for (int rh = 0; rh < 2; rh++) {
            float s = 0.f, s2 = 0.f;
#pragma unroll
            for (int nt = 0; nt < 4; nt++)
#pragma unroll
                for (int b = 0; b < 2; b++) {
                    float v = acc3[mt][nt][2 * rh + b];
                    s += v; s2 += v * v;
                }
            s += __shfl_xor_sync(0xFFFFFFFF, s, 1);
            s += __shfl_xor_sync(0xFFFFFFFF, s, 2);
            s2 += __shfl_xor_sync(0xFFFFFFFF, s2, 1);
            s2 += __shfl_xor_sync(0xFFFFFFFF, s2, 2);
            if (qk == 0) {
                int rr = m0 + 16 * mt + r0 + 8 * rh;
                red_s[rr][warp_n] = s;
                red_s2[rr][warp_n] = s2;
            }
        }
    __syncthreads();
    if (tid < TILE_E) {
        float s = red_s[tid][0] + red_s[tid][1] + red_s[tid][2] + red_s[tid][3];
        float s2 = red_s2[tid][0] + red_s2[tid][1] + red_s2[tid][2] + red_s2[tid][3];
        float mu = s * (1.f / 128.f);
        float var = s2 * (1.f / 128.f) - mu * mu;
        mu_s[tid] = mu;
        rinv_s[tid] = rsqrtf(var + EPS);
    }
    __syncthreads();
#pragma unroll
    for (int mt = 0; mt < 2; mt++)
#pragma unroll
        for (int nt = 0; nt < 4; nt++) {
            int col = n032 + 8 * nt + cb;
            float2 gv = *(const float2*)(g2 + col);
            float2 bv = *(const float2*)(be2 + col);
#pragma unroll
            for (int rh = 0; rh < 2; rh++) {
                int rr = m0 + 16 * mt + r0 + 8 * rh;
                int eg = e0 + rr;
                if (eg < E) {
                    float mu = mu_s[rr], ri = rinv_s[rr];
                    float2 ov;
                    ov.x = (acc3[mt][nt][2 * rh + 0] - mu) * ri * gv.x + bv.x;
                    ov.y = (acc3[mt][nt][2 * rh + 1] - mu) * ri * gv.y + bv.y;
                    *(float2*)(out + (size_t)eg * D_OUT + col) = ov;
                }
            }
        }
}

// ---------------------------------------------------------------------------
// launch
// ---------------------------------------------------------------------------
extern "C" void kernel_launch(void* const* d_in, const int* in_sizes, int n_in,
                              void* d_out, int out_size) {
    const void* p[16];
    int sz[16];
    int m = 0;
    for (int i = 0; i < n_in && m < 16; i++) {
        if (in_sizes[i] == 1) continue;
        p[m] = d_in[i];
        sz[m] = in_sizes[i];
        m++;
    }
    const float* x          = (const float*)p[0];
    const int*   edge_index = (const int*)p[1];
    const float* edge_attr  = (const float*)p[2];
    const float* mask       = (const float*)p[3];
    const float* We         = (const float*)p[4];
    const float* bE         = (const float*)p[5];
    const float* W1         = (const float*)p[6];
    const float* b1         = (const float*)p[7];
    const float* W2         = (const float*)p[8];
    const float* b2         = (const float*)p[9];
    const float* g1         = (const float*)p[10];
    const float* be1        = (const float*)p[11];
    const float* g2         = (const float*)p[12];
    const float* be2        = (const float*)p[13];

    const int N = sz[0] / 6;
    const int E = sz[3];

    float* out_node = (float*)d_out;                     // [N,134]
    float* out_edge = out_node + (size_t)N * D_NODEREP;  // [E,128]

    {
        int total4 = N * (D_IN / 4);
        zero_kernel<<<(total4 + 255) / 256, 256>>>(N);
    }
    {
        agg_kernel<<<(E + 7) / 8, 256>>>(edge_attr, mask, edge_index, E);
    }
    {
        const int smem = NP_SMEM_FLOATS * (int)sizeof(float);
        cudaFuncSetAttribute(nodeproj_kernel, cudaFuncAttributeMaxDynamicSharedMemorySize, smem);
        int blocks = (N + TILE_N - 1) / TILE_N;
        nodeproj_kernel<<<blocks, NPTHREADS, smem>>>(x, We, out_node, N);
    }
    {
        const int smem = E_SMEM_FLOATS * (int)sizeof(float);
        cudaFuncSetAttribute(edge_kernel, cudaFuncAttributeMaxDynamicSharedMemorySize, smem);
        int blocks = (E + TILE_E - 1) / TILE_E;
        edge_kernel<<<blocks, ETHREADS, smem>>>(edge_attr, edge_index,
                                                We, bE, W1, b1, W2, b2,
                                                g1, be1, g2, be2, out_edge, E);
    }
}

// round 16
// speedup vs baseline: 1.4306x; 1.3857x over previous
#include <cuda_runtime.h>
#include <cuda_bf16.h>
#include <cuda_fp16.h>
#include <cstdint>

// ---------------------------------------------------------------------------
// Problem constants
// ---------------------------------------------------------------------------
#define MAXN 50000
#define D_IN 128
#define D_OUT 128
#define D_NODEREP 134  // 128 + 6
#define DH 256
#define EPS 1e-5f

#define TILE_E 64
#define ETHREADS 256

// ---- edge kernel smem layout ----
// Region0: psum fp32 [64 x 132] = 8448 floats; h (fp16) overlays it after LN1
//          (h: 64 rows x 68 b32 = 4352 b32)
// Region1: featz/t fp16 [64 x 68 b32] = 4352 floats
// Region2: weight ring, 4 slots x 1536 b32 (chunk image = 128 n x 12 b32)
#define S_PS 132
#define SA 68                         // fp16 tile row stride in b32 units
#define FZ_OFF 8448
#define WB_OFF (FZ_OFF + 4352)        // 12800
#define WB_SLOT 1536
#define E_SMEM_FLOATS (WB_OFF + 4 * WB_SLOT)  // 18944 floats = 75776 B

// ---- node projection kernel (R14 config, proven) ----
#define TILE_N 64
#define NPTHREADS 256
#define KPAD_P 144
#define NCH_P 18
#define S_P 164
#define S_WB 264
#define NP_A_FLOATS (TILE_N * S_P)
#define NP_WSLOT 2112
#define NP_SMEM_FLOATS (NP_A_FLOATS + 4 * NP_WSLOT)

// Scratch (static device globals: no allocation allowed)
__device__ float g_agg[(size_t)MAXN * D_IN];
__device__ float g_den[MAXN];
__device__ float g_P[(size_t)MAXN * 256];      // [N][Pa(128) | Pb(128)]
// fp16 transposed weight chunk images ([n][k] packed, 12 b32 per row)
__device__ unsigned g_WecT[12288];             // 8 chunks  x 128n x 12
__device__ unsigned g_W1T[24576];              // 16 chunks x 128n x 12
__device__ unsigned g_W2T[24576];              // 16 chunks x 128n x 12

// ---------------------------------------------------------------------------
// helpers
// ---------------------------------------------------------------------------
__device__ __forceinline__ unsigned f2tf(float f) {
    unsigned u;
    asm("cvt.rna.tf32.f32 %0, %1;" : "=r"(u) : "f"(f));
    return u;
}

__device__ __forceinline__ unsigned h2u(float a, float b) {
    __half2 h = __floats2half2_rn(a, b);
    return *reinterpret_cast<unsigned*>(&h);
}
__device__ __forceinline__ float2 u2f2(unsigned u) {
    __half2 h = *reinterpret_cast<__half2*>(&u);
    return __half22float2(h);
}

__device__ __forceinline__ void mma_f16(float* c, const unsigned* a,
                                        unsigned b0, unsigned b1) {
    asm volatile(
        "mma.sync.aligned.m16n8k16.row.col.f32.f16.f16.f32 "
        "{%0,%1,%2,%3},{%4,%5,%6,%7},{%8,%9},{%0,%1,%2,%3};\n"
        : "+f"(c[0]), "+f"(c[1]), "+f"(c[2]), "+f"(c[3])
        : "r"(a[0]), "r"(a[1]), "r"(a[2]), "r"(a[3]), "r"(b0), "r"(b1));
}

__device__ __forceinline__ void mma_tf32(float* c, const unsigned* a,
                                         unsigned b0, unsigned b1) {
    asm volatile(
        "mma.sync.aligned.m16n8k8.row.col.f32.tf32.tf32.f32 "
        "{%0,%1,%2,%3},{%4,%5,%6,%7},{%8,%9},{%0,%1,%2,%3};\n"
        : "+f"(c[0]), "+f"(c[1]), "+f"(c[2]), "+f"(c[3])
        : "r"(a[0]), "r"(a[1]), "r"(a[2]), "r"(a[3]), "r"(b0), "r"(b1));
}

__device__ __forceinline__ void cp16(float* dst_smem, const float* src, bool pred) {
    unsigned d = (unsigned)__cvta_generic_to_shared(dst_smem);
    int sz = pred ? 16 : 0;
    asm volatile("cp.async.cg.shared.global [%0], [%1], 16, %2;\n"
                 :: "r"(d), "l"(src), "r"(sz));
}
__device__ __forceinline__ void cp_commit() {
    asm volatile("cp.async.commit_group;\n");
}
template <int N>
__device__ __forceinline__ void cp_wait() {
    asm volatile("cp.async.wait_group %0;\n" :: "n"(N));
}

// ---------------------------------------------------------------------------
// Kernel 1: zero the scratch (float4)
// ---------------------------------------------------------------------------
__global__ void zero_kernel(int N) {
    int idx = blockIdx.x * blockDim.x + threadIdx.x;
    int total4 = N * (D_IN / 4);
    if (idx < total4) ((float4*)g_agg)[idx] = make_float4(0.f, 0.f, 0.f, 0.f);
    if (idx < N) g_den[idx] = 0.f;
}

// ---------------------------------------------------------------------------
// Kernel 2: masked scatter-add aggregation (warp per edge, float4 atomics)
// ---------------------------------------------------------------------------
__global__ void agg_kernel(const float* __restrict__ edge_attr,
                           const float* __restrict__ mask,
                           const int* __restrict__ edge_index, int E) {
    int w = (blockIdx.x * blockDim.x + threadIdx.x) >> 5;
    int lane = threadIdx.x & 31;
    if (w >= E) return;
    float m = mask[w];
    if (m == 0.f) return;
    int col = edge_index[E + w];
    const float4* a = (const float4*)(edge_attr + (size_t)w * D_IN);
    float4* dst = (float4*)(g_agg + (size_t)col * D_IN);
    float4 v = a[lane];
    v.x *= m; v.y *= m; v.z *= m; v.w *= m;
    atomicAdd(dst + lane, v);
    if (lane == 0) atomicAdd(g_den + col, m);
}

// ---------------------------------------------------------------------------
// Kernel 3: weight prep — fp16 transposed chunk images [n][k], padded rows.
// chunk image row n: 8 data b32 (16 k-halves) + 4 pad b32 (zero).
// ---------------------------------------------------------------------------
__global__ void prep_kernel(const float* __restrict__ We,
                            const float* __restrict__ W1,
                            const float* __restrict__ W2) {
    int i = blockIdx.x * 256 + threadIdx.x;
    if (i >= 61440) return;
    unsigned val = 0;
    unsigned* dst;
    if (i < 12288) {                    // We_c^T: 8 chunks over k 0..127
        int ch = i / 1536, rem = i - ch * 1536;
        int n = rem / 12, j = rem - n * 12;
        if (j < 8) {
            int k = ch * 16 + 2 * j;
            float w0 = We[(size_t)(2 * D_NODEREP + k) * D_OUT + n];
            float w1 = We[(size_t)(2 * D_NODEREP + k + 1) * D_OUT + n];
            val = h2u(w0, w1);
        }
        dst = g_WecT + i;
    } else if (i < 36864) {             // W1^T: 16 chunks = 2 col-halves x 8
        int t = i - 12288;
        int hf = t / 12288;
        int r = t - hf * 12288;
        int ch = r / 1536, rem = r - ch * 1536;
        int n = rem / 12, j = rem - n * 12;
        if (j < 8) {
            int k = ch * 16 + 2 * j;
            float w0 = W1[(size_t)k * DH + hf * 128 + n];
            float w1 = W1[(size_t)(k + 1) * DH + hf * 128 + n];
            val = h2u(w0, w1);
        }
        dst = g_W1T + t;
    } else {                            // W2^T: 16 chunks over k 0..255
        int t = i - 36864;
        int ch = t / 1536, rem = t - ch * 1536;
        int n = rem / 12, j = rem - n * 12;
        if (j < 8) {
            int k = ch * 16 + 2 * j;
            float w0 = W2[(size_t)k * D_OUT + n];
            float w1 = W2[(size_t)(k + 1) * D_OUT + n];
            val = h2u(w0, w1);
        }
        dst = g_W2T + t;
    }
    *dst = val;
}

// ---------------------------------------------------------------------------
// Kernel 4: node projection (R14 config, tf32 — unchanged, proven)
// ---------------------------------------------------------------------------
__global__ void __launch_bounds__(NPTHREADS, 3)
nodeproj_kernel(const float* __restrict__ x,
                const float* __restrict__ We,
                float* __restrict__ out_node, int N) {
    extern __shared__ float sm[];
    float* A = sm;
    float* wb = sm + NP_A_FLOATS;
    __shared__ float rden_s[TILE_N];

    const int tid = threadIdx.x;
    const int lane = tid & 31;
    const int wid = tid >> 5;
    const int n0blk = blockIdx.x * TILE_N;

    const int m0 = 16 * (wid >> 1);
    const int n0 = 128 * (wid & 1);
    const int r0 = lane >> 2;
    const int qk = lane & 3;
    const int cb = 2 * qk;

    auto issue_w = [&](int ch, int slot) {
        float* dst = wb + slot * NP_WSLOT;
        int kb = ch * 8;
#pragma unroll
        for (int j = 0; j < 2; j++) {
            int i = tid + j * NPTHREADS;
            int r = i >> 6;
            int c4 = (i & 63) * 4;
            int k = kb + r;
            const float* src = (c4 < 128)
                ? We + (size_t)k * D_OUT + c4
                : We + (size_t)(D_NODEREP + k) * D_OUT + (c4 - 128);
            cp16(dst + r * S_WB + c4, src, k < D_NODEREP);
        }
        cp_commit();
    };

    issue_w(0, 0);
    issue_w(1, 1);
    issue_w(2, 2);

    if (tid < TILE_N) {
        int n = n0blk + tid;
        float d = (n < N) ? g_den[n] : 0.f;
        rden_s[tid] = 1.0f / (d + 1.0f);
    }
    __syncthreads();

    for (int idx = tid; idx < TILE_N * KPAD_P; idx += NPTHREADS) {
        int e = idx / KPAD_P;
        int k = idx - e * KPAD_P;
        int n = n0blk + e;
        float v = 0.f;
        if (n < N && k < D_NODEREP) {
            if (k < D_IN)
                v = g_agg[(size_t)n * D_IN + k] * rden_s[e];
            else
                v = x[n * 6 + (k - D_IN)];
            out_node[(size_t)n * D_NODEREP + k] = v;
        }
        A[e * S_P + k] = v;
    }

    float acc[16][4];
#pragma unroll
    for (int nt = 0; nt < 16; nt++)
#pragma unroll
        for (int q = 0; q < 4; q++) acc[nt][q] = 0.f;

    for (int ch = 0; ch < NCH_P; ch++) {
        if (ch < NCH_P - 2) cp_wait<2>();
        else if (ch == NCH_P - 2) cp_wait<1>();
        else cp_wait<0>();
        __syncthreads();
        const float* cur = wb + (ch & 3) * NP_WSLOT;
        int k0 = ch * 8;
        const float* ap = A + (m0 + r0) * S_P + k0 + qk;
        unsigned a[4];
        a[0] = f2tf(ap[0]);
        a[1] = f2tf(ap[8 * S_P]);
        a[2] = f2tf(ap[4]);
        a[3] = f2tf(ap[8 * S_P + 4]);
#pragma unroll
        for (int nt = 0; nt < 16; nt++) {
            const float* bp = cur + qk * S_WB + n0 + 8 * nt + r0;
            mma_tf32(acc[nt], a, __float_as_uint(bp[0]),
                     __float_as_uint(bp[4 * S_WB]));
        }
        if (ch + 3 < NCH_P) issue_w(ch + 3, (ch + 3) & 3);
    }

#pragma unroll
    for (int nt = 0; nt < 16; nt++) {
        int col = n0 + 8 * nt + cb;
#pragma unroll
        for (int q = 0; q < 4; q++) {
            int rr = m0 + r0 + (q >> 1) * 8;
            int cc = col + (q & 1);
            int n = n0blk + rr;
            if (n < N) g_P[(size_t)n * 256 + cc] = acc[nt][q];
        }
    }
}

// ---------------------------------------------------------------------------
// Kernel 5: fused edge MLP on fp16 m16n8k16 mma.sync.
// 64 edges/block, 256 threads (8 warps, warp tile m32 x n32), 2 blocks/SM.
// Ring: 4 slots x 1536 b32 chunk images, depth-3 prefetch.
// Ordering: wait -> barrier -> compute(ch) -> issue(ch+3)  (R12-proven).
// ---------------------------------------------------------------------------
__global__ void __launch_bounds__(ETHREADS, 2)
edge_kernel(const float* __restrict__ edge_attr,
            const int* __restrict__ edge_index,
            const float* __restrict__ bE,
            const float* __restrict__ b1, const float* __restrict__ b2,
            const float* __restrict__ g1, const float* __restrict__ be1,
            const float* __restrict__ g2, const float* __restrict__ be2,
            float* __restrict__ out, int E) {
    extern __shared__ float sm[];
    float* ps = sm;                          // psum fp32 [64 x 132]
    unsigned* hb = (unsigned*)sm;            // h fp16 overlay [64 x 68]
    unsigned* fz = (unsigned*)(sm + FZ_OFF); // featz / t fp16 [64 x 68]
    float* wbf = sm + WB_OFF;                // ring
    __shared__ int rows_s[TILE_E], cols_s[TILE_E];
    __shared__ float red_s[TILE_E][4];
    __shared__ float red_s2[TILE_E][4];
    __shared__ float mu_s[TILE_E], rinv_s[TILE_E];

    const int tid = threadIdx.x;
    const int lane = tid & 31;
    const int wid = tid >> 5;
    const int e0 = blockIdx.x * TILE_E;

    const int m0 = 32 * (wid & 1);     // 0 or 32
    const int warp_n = wid >> 1;       // 0..3
    const int n032 = 32 * warp_n;
    const int r0 = lane >> 2;
    const int qk = lane & 3;
    const int cb = 2 * qk;

    auto issue_img = [&](const unsigned* img, int ch, int slot) {
        float* dst = wbf + slot * WB_SLOT;
        const float* src = (const float*)(img + ch * WB_SLOT);
#pragma unroll
        for (int j = 0; j < 2; j++) {
            int i = tid + j * ETHREADS;
            if (i < 384) cp16(dst + i * 4, src + i * 4, true);
        }
        cp_commit();
    };

    if (tid < TILE_E) {
        int eg = e0 + tid;
        rows_s[tid] = (eg < E) ? edge_index[eg] : 0;
        cols_s[tid] = (eg < E) ? edge_index[E + eg] : 0;
    }

    // GEMM1 prologue (depth 3) — overlaps gathers
    issue_img(g_WecT, 0, 0);
    issue_img(g_WecT, 1, 1);
    issue_img(g_WecT, 2, 2);

    // edge_attr tile -> fz (fp16 packed), float4 coalesced
    for (int idx = tid; idx < TILE_E * 32; idx += ETHREADS) {
        int e = idx >> 5;
        int c4 = (idx & 31) * 4;
        int eg = e0 + e;
        float4 v = make_float4(0.f, 0.f, 0.f, 0.f);
        if (eg < E) v = *(const float4*)(edge_attr + (size_t)eg * D_IN + c4);
        uint2 hv;
        hv.x = h2u(v.x, v.y);
        hv.y = h2u(v.z, v.w);
        *(uint2*)(fz + e * SA + (idx & 31) * 2) = hv;
    }
    __syncthreads();  // rows_s/cols_s ready

    // psum = Pa[row] + Pb[col]  (fp32, stride 132)
    for (int idx = tid; idx < TILE_E * 32; idx += ETHREADS) {
        int e = idx >> 5;
        int c4 = (idx & 31) * 4;
        float4 pa = *(const float4*)(g_P + (size_t)rows_s[e] * 256 + c4);
        float4 pb = *(const float4*)(g_P + (size_t)cols_s[e] * 256 + 128 + c4);
        pa.x += pb.x; pa.y += pb.y; pa.z += pb.z; pa.w += pb.w;
        *(float4*)(ps + e * S_PS + c4) = pa;
    }

    // ================= GEMM1: feat[64,128] @ We_c  (8 chunks k16) =========
    float acc1[2][4][4];
#pragma unroll
    for (int mt = 0; mt < 2; mt++)
#pragma unroll
        for (int nt = 0; nt < 4; nt++)
#pragma unroll
            for (int q = 0; q < 4; q++) acc1[mt][nt][q] = 0.f;

    {
        const int NCH = 8;
        for (int ch = 0; ch < NCH; ch++) {
            if (ch < NCH - 2) cp_wait<2>();
            else if (ch == NCH - 2) cp_wait<1>();
            else cp_wait<0>();
            __syncthreads();
            const unsigned* cur = (const unsigned*)(wbf + (ch & 3) * WB_SLOT);
            unsigned a[2][4];
#pragma unroll
            for (int mt = 0; mt < 2; mt++) {
                const unsigned* ap = fz + (m0 + 16 * mt + r0) * SA + ch * 8 + qk;
                a[mt][0] = ap[0];
                a[mt][1] = ap[8 * SA];
                a[mt][2] = ap[4];
                a[mt][3] = ap[8 * SA + 4];
            }
#pragma unroll
            for (int nt = 0; nt < 4; nt++) {
                const unsigned* bp = cur + (n032 + 8 * nt + r0) * 12 + qk;
                unsigned b0 = bp[0], b1w = bp[4];
                mma_f16(acc1[0][nt], a[0], b0, b1w);
                mma_f16(acc1[1][nt], a[1], b0, b1w);
            }
            if (ch + 3 < NCH) issue_img(g_WecT, ch + 3, (ch + 3) & 3);
        }
    }

    // GEMM2(hf=0) prologue — slots 0,1,2 last read at ch 4,5,6 (all done)
    issue_img(g_W1T, 0, 0);
    issue_img(g_W1T, 1, 1);
    issue_img(g_W1T, 2, 2);

    // ---- GEMM1 epilogue with fused LN1 (register-resident) ----
#pragma unroll
    for (int mt = 0; mt < 2; mt++)
#pragma unroll
        for (int nt = 0; nt < 4; nt++) {
            int col = n032 + 8 * nt + cb;
            float2 bev = *(const float2*)(bE + col);
#pragma unroll
            for (int rh = 0; rh < 2; rh++) {
                int rr = m0 + 16 * mt + r0 + 8 * rh;
                float2 fzv = u2f2(fz[rr * SA + (col >> 1)]);
                float2 pv = *(float2*)(ps + rr * S_PS + col);
                acc1[mt][nt][2 * rh + 0] += bev.x + fzv.x + pv.x;
                acc1[mt][nt][2 * rh + 1] += bev.y + fzv.y + pv.y;
            }
        }
#pragma unroll
    for (int mt = 0; mt < 2; mt++)
#pragma unroll
        for (int rh = 0; rh < 2; rh++) {
            float s = 0.f, s2 = 0.f;
#pragma unroll
            for (int nt = 0; nt < 4; nt++)
#pragma unroll
                for (int b = 0; b < 2; b++) {
                    float v = acc1[mt][nt][2 * rh + b];
                    s += v; s2 += v * v;
                }
            s += __shfl_xor_sync(0xFFFFFFFF, s, 1);
            s += __shfl_xor_sync(0xFFFFFFFF, s, 2);
            s2 += __shfl_xor_sync(0xFFFFFFFF, s2, 1);
            s2 += __shfl_xor_sync(0xFFFFFFFF, s2, 2);
            if (qk == 0) {
                int rr = m0 + 16 * mt + r0 + 8 * rh;
                red_s[rr][warp_n] = s;
                red_s2[rr][warp_n] = s2;
            }
        }
    __syncthreads();
    if (tid < TILE_E) {
        float s = red_s[tid][0] + red_s[tid][1] + red_s[tid][2] + red_s[tid][3];
        float s2 = red_s2[tid][0] + red_s2[tid][1] + red_s2[tid][2] + red_s2[tid][3];
        float mu = s * (1.f / 128.f);
        float var = s2 * (1.f / 128.f) - mu * mu;
        mu_s[tid] = mu;
        rinv_s[tid] = rsqrtf(var + EPS);
    }
    __syncthreads();
    // normalize, store h as packed fp16 (overlays dead psum region)
#pragma unroll
    for (int mt = 0; mt < 2; mt++)
#pragma unroll
        for (int nt = 0; nt < 4; nt++) {
            int col = n032 + 8 * nt + cb;
            float2 gv = *(const float2*)(g1 + col);
            float2 bv = *(const float2*)(be1 + col);
#pragma unroll
            for (int rh = 0; rh < 2; rh++) {
                int rr = m0 + 16 * mt + r0 + 8 * rh;
                float mu = mu_s[rr], ri = rinv_s[rr];
                float h0 = (acc1[mt][nt][2 * rh + 0] - mu) * ri * gv.x + bv.x;
                float h1 = (acc1[mt][nt][2 * rh + 1] - mu) * ri * gv.y + bv.y;
                hb[rr * SA + (col >> 1)] = h2u(h0, h1);
            }
        }

    // ============ GEMM2+GEMM3 in two 128-halves, acc3 persistent =========
    float acc3[2][4][4];
#pragma unroll
    for (int mt = 0; mt < 2; mt++)
#pragma unroll
        for (int nt = 0; nt < 4; nt++)
#pragma unroll
            for (int q = 0; q < 4; q++) acc3[mt][nt][q] = 0.f;

#pragma unroll 1
    for (int hf = 0; hf < 2; hf++) {
        // ---- GEMM2 half: t_half = relu(h @ W1[:, hf*128:+128] + b1h) ----
        {
            float acc2[2][4][4];
#pragma unroll
            for (int mt = 0; mt < 2; mt++)
#pragma unroll
                for (int nt = 0; nt < 4; nt++)
#pragma unroll
                    for (int q = 0; q < 4; q++) acc2[mt][nt][q] = 0.f;

            if (hf) {
                issue_img(g_W1T, 8 + 0, 0);
                issue_img(g_W1T, 8 + 1, 1);
                issue_img(g_W1T, 8 + 2, 2);
            }
            const int NCH = 8;
            for (int ch = 0; ch < NCH; ch++) {
                if (ch < NCH - 2) cp_wait<2>();
                else if (ch == NCH - 2) cp_wait<1>();
                else cp_wait<0>();
                __syncthreads();
                const unsigned* cur = (const unsigned*)(wbf + (ch & 3) * WB_SLOT);
                unsigned a[2][4];
#pragma unroll
                for (int mt = 0; mt < 2; mt++) {
                    const unsigned* ap = hb + (m0 + 16 * mt + r0) * SA + ch * 8 + qk;
                    a[mt][0] = ap[0];
                    a[mt][1] = ap[8 * SA];
                    a[mt][2] = ap[4];
                    a[mt][3] = ap[8 * SA + 4];
                }
#pragma unroll
                for (int nt = 0; nt < 4; nt++) {
                    const unsigned* bp = cur + (n032 + 8 * nt + r0) * 12 + qk;
                    unsigned b0 = bp[0], b1w = bp[4];
                    mma_f16(acc2[0][nt], a[0], b0, b1w);
                    mma_f16(acc2[1][nt], a[1], b0, b1w);
                }
                if (ch + 3 < NCH) issue_img(g_W1T, hf * 8 + ch + 3, (ch + 3) & 3);
            }
            __syncthreads();  // ring reads done; fz free for t

            // GEMM3 half prologue — copies land during t-store
            issue_img(g_W2T, hf * 8 + 0, 0);
            issue_img(g_W2T, hf * 8 + 1, 1);
            issue_img(g_W2T, hf * 8 + 2, 2);

            // t_half -> fz (packed fp16)
#pragma unroll
            for (int mt = 0; mt < 2; mt++)
#pragma unroll
                for (int nt = 0; nt < 4; nt++) {
                    int col = n032 + 8 * nt + cb;
                    float2 b1v = *(const float2*)(b1 + hf * 128 + col);
#pragma unroll
                    for (int rh = 0; rh < 2; rh++) {
                        int rr = m0 + 16 * mt + r0 + 8 * rh;
                        float t0 = fmaxf(acc2[mt][nt][2 * rh + 0] + b1v.x, 0.f);
                        float t1 = fmaxf(acc2[mt][nt][2 * rh + 1] + b1v.y, 0.f);
                        fz[rr * SA + (col >> 1)] = h2u(t0, t1);
                    }
                }
        }
        __syncthreads();

        // ---- GEMM3 half: acc3 += t_half @ W2[hf*128:+128, :] ----
        {
            const int NCH = 8;
            for (int ch = 0; ch < NCH; ch++) {
                if (ch < NCH - 2) cp_wait<2>();
                else if (ch == NCH - 2) cp_wait<1>();
                else cp_wait<0>();
                __syncthreads();
                const unsigned* cur = (const unsigned*)(wbf + (ch & 3) * WB_SLOT);
                unsigned a[2][4];
#pragma unroll
                for (int mt = 0; mt < 2; mt++) {
                    const unsigned* ap = fz + (m0 + 16 * mt + r0) * SA + ch * 8 + qk;
                    a[mt][0] = ap[0];
                    a[mt][1] = ap[8 * SA];
                    a[mt][2] = ap[4];
                    a[mt][3] = ap[8 * SA + 4];
                }
#pragma unroll
                for (int nt = 0; nt < 4; nt++) {
                    const unsigned* bp = cur + (n032 + 8 * nt + r0) * 12 + qk;
                    unsigned b0 = bp[0], b1w = bp[4];
                    mma_f16(acc3[0][nt], a[0], b0, b1w);
                    mma_f16(acc3[1][nt], a[1], b0, b1w);
                }
                if (ch + 3 < NCH) issue_img(g_W2T, hf * 8 + ch + 3, (ch + 3) & 3);
            }
        }
        __syncthreads();  // fz reads done before next hf overwrites
    }

    // ---- GEMM3 epilogue with fused LN2 -> global out ----
#pragma unroll
    for (int mt = 0; mt < 2; mt++)
#pragma unroll
        for (int nt = 0; nt < 4; nt++) {
            int col = n032 + 8 * nt + cb;
            float2 b2v = *(const float2*)(b2 + col);
#pragma unroll
            for (int rh = 0; rh < 2; rh++) {
                int rr = m0 + 16 * mt + r0 + 8 * rh;
                float2 hv = u2f2(hb[rr * SA + (col >> 1)]);
                acc3[mt][nt][2 * rh + 0] += b2v.x + hv.x;
                acc3[mt][nt][2 * rh + 1] += b2v.y + hv.y;
            }
        }
#pragma unroll
    for (int mt = 0; mt < 2; mt++)
#pragma unroll
        for (int rh = 0; rh < 2; rh++) {
            float s = 0.f, s2 = 0.f;
#pragma unroll
            for (int nt = 0; nt < 4; nt++)
#pragma unroll
                for (int b = 0; b < 2; b++) {
                    float v = acc3[mt][nt][2 * rh + b];
                    s += v; s2 += v * v;
                }
            s += __shfl_xor_sync(0xFFFFFFFF, s, 1);
            s += __shfl_xor_sync(0xFFFFFFFF, s, 2);
            s2 += __shfl_xor_sync(0xFFFFFFFF, s2, 1);
            s2 += __shfl_xor_sync(0xFFFFFFFF, s2, 2);
            if (qk == 0) {
                int rr = m0 + 16 * mt + r0 + 8 * rh;
                red_s[rr][warp_n] = s;
                red_s2[rr][warp_n] = s2;
            }
        }
    __syncthreads();
    if (tid < TILE_E) {
        float s = red_s[tid][0] + red_s[tid][1] + red_s[tid][2] + red_s[tid][3];
        float s2 = red_s2[tid][0] + red_s2[tid][1] + red_s2[tid][2] + red_s2[tid][3];
        float mu = s * (1.f / 128.f);
        float var = s2 * (1.f / 128.f) - mu * mu;
        mu_s[tid] = mu;
        rinv_s[tid] = rsqrtf(var + EPS);
    }
    __syncthreads();
#pragma unroll
    for (int mt = 0; mt < 2; mt++)
#pragma unroll
        for (int nt = 0; nt < 4; nt++) {
            int col = n032 + 8 * nt + cb;
            float2 gv = *(const float2*)(g2 + col);
            float2 bv = *(const float2*)(be2 + col);
#pragma unroll
            for (int rh = 0; rh < 2; rh++) {
                int rr = m0 + 16 * mt + r0 + 8 * rh;
                int eg = e0 + rr;
                if (eg < E) {
                    float mu = mu_s[rr], ri = rinv_s[rr];
                    float2 ov;
                    ov.x = (acc3[mt][nt][2 * rh + 0] - mu) * ri * gv.x + bv.x;
                    ov.y = (acc3[mt][nt][2 * rh + 1] - mu) * ri * gv.y + bv.y;
                    *(float2*)(out + (size_t)eg * D_OUT + col) = ov;
                }
            }
        }
}

// ---------------------------------------------------------------------------
// launch
// ---------------------------------------------------------------------------
extern "C" void kernel_launch(void* const* d_in, const int* in_sizes, int n_in,
                              void* d_out, int out_size) {
    const void* p[16];
    int sz[16];
    int m = 0;
    for (int i = 0; i < n_in && m < 16; i++) {
        if (in_sizes[i] == 1) continue;
        p[m] = d_in[i];
        sz[m] = in_sizes[i];
        m++;
    }
    const float* x          = (const float*)p[0];
    const int*   edge_index = (const int*)p[1];
    const float* edge_attr  = (const float*)p[2];
    const float* mask       = (const float*)p[3];
    const float* We         = (const float*)p[4];
    const float* bE         = (const float*)p[5];
    const float* W1         = (const float*)p[6];
    const float* b1         = (const float*)p[7];
    const float* W2         = (const float*)p[8];
    const float* b2         = (const float*)p[9];
    const float* g1         = (const float*)p[10];
    const float* be1        = (const float*)p[11];
    const float* g2         = (const float*)p[12];
    const float* be2        = (const float*)p[13];

    const int N = sz[0] / 6;
    const int E = sz[3];

    float* out_node = (float*)d_out;                     // [N,134]
    float* out_edge = out_node + (size_t)N * D_NODEREP;  // [E,128]

    {
        int total4 = N * (D_IN / 4);
        zero_kernel<<<(total4 + 255) / 256, 256>>>(N);
    }
    {
        prep_kernel<<<(61440 + 255) / 256, 256>>>(We, W1, W2);
    }
    {
        agg_kernel<<<(E + 7) / 8, 256>>>(edge_attr, mask, edge_index, E);
    }
    {
        const int smem = NP_SMEM_FLOATS * (int)sizeof(float);
        cudaFuncSetAttribute(nodeproj_kernel, cudaFuncAttributeMaxDynamicSharedMemorySize, smem);
        int blocks = (N + TILE_N - 1) / TILE_N;
        nodeproj_kernel<<<blocks, NPTHREADS, smem>>>(x, We, out_node, N);
    }
    {
        const int smem = E_SMEM_FLOATS * (int)sizeof(float);
        cudaFuncSetAttribute(edge_kernel, cudaFuncAttributeMaxDynamicSharedMemorySize, smem);
        int blocks = (E + TILE_E - 1) / TILE_E;
        edge_kernel<<<blocks, ETHREADS, smem>>>(edge_attr, edge_index,
                                                bE, b1, b2, g1, be1, g2, be2,
                                                out_edge, E);
    }
}